// round 1
// baseline (speedup 1.0000x reference)
#include <cuda_runtime.h>
#include <cstdint>

// ---------------------------------------------------------------------------
// WRF RK3 step on GB (sm_100a). Pure stencil, HBM-bound.
// Grid: NZ=48 levels (cell centers), NY=NX=384 periodic in x,y.
// Staggering: U on x-faces (385), V on y-faces (385), W & Phi on 47 interior
// z-interfaces, Theta/Mu at centers.
// ---------------------------------------------------------------------------

constexpr int NX  = 384, NY = 384, NZ = 48;
constexpr int NXP = NX + 1;          // 385 x-faces
constexpr int NYP = NY + 1;          // 385 y-faces
constexpr int NZW = NZ - 1;          // 47 interior interfaces (W, Phi, Omega, w)
constexpr int NZI = NZ + 1;          // 49 interfaces (pzh)
constexpr int PC  = NX * NY;         // 147456 per-level plane
constexpr int SZC = NZ  * PC;        // 7,077,888  (Theta, Mu, p, alpha, theta, Phih)
constexpr int SZW = NZW * PC;        // 6,930,432  (W, Phi, Omega, omega, w)
constexpr int SZU = NZ * NY * NXP;   // 7,096,320
constexpr int SZV = NZ * NYP * NX;   // 7,096,320
constexpr int SZI = NZI * PC;        // 7,225,344  (pzh)

constexpr float PREF = 100000.0f;
constexpr float RDC  = 287.0f;
constexpr float GRAV = 9.81f;
constexpr float DXC  = 1000.0f;
constexpr float DYC  = 1000.0f;
#define DZF ((float)(1.0 / 49.0))

// Accurate f32 pow that bit-matches XLA's libdevice lowering regardless of
// -use_fast_math (under fast math, powf would become the inaccurate __powf).
#ifdef __FAST_MATH__
extern "C" __device__ float __nv_powf(float, float);
#define POWF(a, b) __nv_powf((a), (b))
#else
#define POWF(a, b) powf((a), (b))
#endif

// ---------------------------------------------------------------------------
// Scratch (static device globals; allocation is forbidden)
// ---------------------------------------------------------------------------
__device__ float g_sU[2 * SZU];
__device__ float g_sV[2 * SZV];
__device__ float g_sW[2 * SZW];
__device__ float g_sT[2 * SZC];
__device__ float g_sM[2 * SZC];
__device__ float g_sP[2 * SZW];

__device__ float g_p[SZC];        // pressure at centers
__device__ float g_alpha[SZC];    // specific volume
__device__ float g_theta[SZC];    // Theta / Mu
__device__ float g_Phih[SZC];     // bar_z(pad_z(Phi,Phi_t,Phi_s)) at centers
__device__ float g_pzh[SZI];      // bar_z(pad_z(p,P_t,P_s)) at 49 interfaces
__device__ float g_Omega[SZW];    // mass-weighted vertical velocity
__device__ float g_omega[SZW];
__device__ float g_w[SZW];        // W / bar_z(Mu)
__device__ float g_u[SZU];        // U / bar_x(pad_x(Mu))
__device__ float g_v[SZV];        // V / bar_y(pad_y(Mu))

__device__ __forceinline__ float read_dt(const void* p) {
    int iv = *(const int*)p;                 // int32 '4' -> 4 ; float 4.0 -> 0x40800000
    if (iv >= -1000000 && iv <= 1000000) return (float)iv;
    return *(const float*)p;
}

// ---------------------------------------------------------------------------
// Derive kernel: one thread per (i,j) column, streams k.
// Computes alpha, theta, p, Phih, pzh, Omega, omega, w for current state.
// ---------------------------------------------------------------------------
__global__ __launch_bounds__(256)
void k_derive(const float* __restrict__ Mu, const float* __restrict__ Th,
              const float* __restrict__ W,  const float* __restrict__ Phi,
              const float* __restrict__ Phit, const float* __restrict__ Phis,
              const float* __restrict__ Pt,   const float* __restrict__ Ps)
{
    int col = blockIdx.x * blockDim.x + threadIdx.x;
    if (col >= PC) return;
    const float pt = Pt[col], ps = Ps[col];
    float phi_lo = Phit[col];            // Phi_p[k]
    float a_prev = 0.f, p_prev = 0.f, m_prev = 0.f;
    for (int k = 0; k < NZ; ++k) {
        const int idx = k * PC + col;
        const float mu = Mu[idx];
        const float phi_hi = (k < NZW) ? Phi[k * PC + col] : Phis[col];  // Phi_p[k+1]
        // alpha = -delta_z(pad_z(Phi,Phi_t,Phi_s)) / Mu    (exact-rounded chain)
        const float dz  = __fdiv_rn(phi_hi - phi_lo, DZF);
        const float al  = __fdiv_rn(-dz, mu);
        const float th  = __fdiv_rn(Th[idx], mu);
        // x = RD*theta/PREF/alpha  (bit-exact vs reference: mul, div, div)
        const float x   = __fdiv_rn(__fdiv_rn(RDC * th, PREF), al);
        const float pk  = POWF(x, 1.4f) * PREF;
        g_alpha[idx] = al;
        g_theta[idx] = th;
        g_p[idx]     = pk;
        g_Phih[idx]  = 0.5f * (phi_lo + phi_hi);
        g_pzh[idx]   = 0.5f * ((k == 0 ? pt : p_prev) + pk);
        if (k > 0) {
            const int iw = (k - 1) * PC + col;
            const float bzm = 0.5f * (m_prev + mu);
            const float bza = 0.5f * (a_prev + al);
            const float wv  = __fdiv_rn(W[iw], bzm);
            const float om  = __fdiv_rn(__fdiv_rn(-wv * GRAV, bza), bzm);
            g_w[iw]     = wv;
            g_omega[iw] = om;
            g_Omega[iw] = om * bzm;
        }
        phi_lo = phi_hi; a_prev = al; p_prev = pk; m_prev = mu;
    }
    g_pzh[NZ * PC + col] = 0.5f * (p_prev + ps);
}

// u = U / bar_x(pad_x(Mu)) on the 385-face grid (periodic wrap)
__global__ __launch_bounds__(256)
void k_derive_u(const float* __restrict__ U, const float* __restrict__ Mu)
{
    int t = blockIdx.x * blockDim.x + threadIdx.x;
    if (t >= SZU) return;
    const int i = t % NXP; const int r = t / NXP;
    const int j = r % NY;  const int k = r / NY;
    const int ii = (i < NX) ? i : 0;
    const int im = (i == 0) ? NX - 1 : i - 1;
    const int bc = k * PC + j * NX;
    const float mf = 0.5f * (Mu[bc + im] + Mu[bc + ii]);
    g_u[t] = __fdiv_rn(U[t], mf);
}

// v = V / bar_y(pad_y(Mu)) on the 385-row grid
__global__ __launch_bounds__(256)
void k_derive_v(const float* __restrict__ V, const float* __restrict__ Mu)
{
    int t = blockIdx.x * blockDim.x + threadIdx.x;
    if (t >= SZV) return;
    const int i = t % NX;  const int r = t / NX;
    const int jf = r % NYP; const int k = r / NYP;
    const int jj = (jf < NY) ? jf : 0;
    const int jm = (jf == 0) ? NY - 1 : jf - 1;
    const float mf = 0.5f * (Mu[k * PC + jm * NX + i] + Mu[k * PC + jj * NX + i]);
    g_v[t] = __fdiv_rn(V[t], mf);
}

// ---------------------------------------------------------------------------
// R_U: one thread per U point (k, j, i-face)
// ---------------------------------------------------------------------------
__global__ __launch_bounds__(256)
void k_RU(const float* __restrict__ U, const float* __restrict__ V,
          const float* __restrict__ Mu,
          const float* __restrict__ U0, float* __restrict__ Uc,
          const void* __restrict__ dtp, double coef)
{
    int t = blockIdx.x * blockDim.x + threadIdx.x;
    if (t >= SZU) return;
    const int i = t % NXP; const int r = t / NXP;
    const int j = r % NY;  const int k = r / NY;

    const int ii = (i < NX) ? i : 0;
    const int im = (i == 0) ? NX - 1 : i - 1;
    const int fL = (i == 0) ? NXP - 1 : i - 1;     // padded face wrap
    const int fR = (i == NXP - 1) ? 0 : i + 1;
    const int jm = (j == 0) ? NY - 1 : j - 1;
    const int jp = (j == NY - 1) ? 0 : j + 1;

    const int bU  = k * (NY * NXP) + j * NXP;
    const float Uf = U[bU + i], UL = U[bU + fL], UR = U[bU + fR];
    const float uf = g_u[bU + i], uL = g_u[bU + fL], uR = g_u[bU + fR];

    // x-advection: -delta_x( bar_x(pad_x(U)) * bar_x(pad_x(u)) )
    const float F0 = 0.5f * (UL + Uf) * 0.5f * (uL + uf);
    const float F1 = 0.5f * (Uf + UR) * 0.5f * (uf + uR);
    float rU = -(F1 - F0) / DXC;

    // y-advection: -delta_y( bar_x(pad_x(V)) * bar_y(pad_y(u)) )
    const int bV = k * (NYP * NX);
    const float Va0 = 0.5f * (V[bV + j       * NX + im] + V[bV + j       * NX + ii]);
    const float Va1 = 0.5f * (V[bV + (j + 1) * NX + im] + V[bV + (j + 1) * NX + ii]);
    const float ub0 = 0.5f * (g_u[k * (NY * NXP) + jm * NXP + i] + uf);
    const float ub1 = 0.5f * (uf + g_u[k * (NY * NXP) + jp * NXP + i]);
    rU += -(Va1 * ub1 - Va0 * ub0) / DYC;

    // z-advection: -delta_z( bar_x(pad_x(pad_z(Omega))) * bar_z(pad_z(u)) )
    float H0 = 0.f, H1 = 0.f;
    if (k >= 1) {
        const int bo = (k - 1) * PC + j * NX;
        const float Om = 0.5f * (g_Omega[bo + im] + g_Omega[bo + ii]);
        const float ub = 0.5f * (g_u[bU - NY * NXP + i] + uf);
        H0 = Om * ub;
    }
    if (k < NZ - 1) {
        const int bo = k * PC + j * NX;
        const float Om = 0.5f * (g_Omega[bo + im] + g_Omega[bo + ii]);
        const float ub = 0.5f * (uf + g_u[bU + NY * NXP + i]);
        H1 = Om * ub;
    }
    rU += -(H1 - H0) / DZF;

    // pressure terms
    const int bc  = k * PC + j * NX;
    const int bc1 = bc + PC;
    const float mufx  = 0.5f * (Mu[bc + im]      + Mu[bc + ii]);
    const float alfx  = 0.5f * (g_alpha[bc + im] + g_alpha[bc + ii]);
    const float dpx   = (g_p[bc + ii] - g_p[bc + im]) / DXC;
    const float Px0   = 0.5f * (g_pzh[bc + im]  + g_pzh[bc + ii]);
    const float Px1   = 0.5f * (g_pzh[bc1 + im] + g_pzh[bc1 + ii]);
    const float dzP   = (Px1 - Px0) / DZF;
    const float dphix = (g_Phih[bc + ii] - g_Phih[bc + im]) / DXC;
    rU += -mufx * alfx * dpx - dzP * dphix;

    const float c = (float)((double)read_dt(dtp) * coef);
    Uc[t] = U0[t] + c * rU;
}

// ---------------------------------------------------------------------------
// R_V: one thread per V point (k, j-face, i)
// ---------------------------------------------------------------------------
__global__ __launch_bounds__(256)
void k_RV(const float* __restrict__ U, const float* __restrict__ V,
          const float* __restrict__ Mu,
          const float* __restrict__ V0, float* __restrict__ Vc,
          const void* __restrict__ dtp, double coef)
{
    int t = blockIdx.x * blockDim.x + threadIdx.x;
    if (t >= SZV) return;
    const int i  = t % NX;  const int r = t / NX;
    const int jf = r % NYP; const int k = r / NYP;

    const int jj = (jf < NY) ? jf : 0;
    const int jm = (jf == 0) ? NY - 1 : jf - 1;
    const int fD = (jf == 0) ? NYP - 1 : jf - 1;   // padded face wrap
    const int fU = (jf == NYP - 1) ? 0 : jf + 1;
    const int imx = (i == 0) ? NX - 1 : i - 1;
    const int ipx = (i == NX - 1) ? 0 : i + 1;

    const int bV = k * (NYP * NX);
    const float Vf = V[bV + jf * NX + i];
    const float VD = V[bV + fD * NX + i];
    const float VU = V[bV + fU * NX + i];
    const float vf = g_v[bV + jf * NX + i];
    const float vD = g_v[bV + fD * NX + i];
    const float vU = g_v[bV + fU * NX + i];

    // x-advection: -delta_x( bar_y(pad_y(U)) * bar_x(pad_x(v)) )
    const int bUjm = k * (NY * NXP) + jm * NXP;
    const int bUjj = k * (NY * NXP) + jj * NXP;
    const float K0 = 0.5f * (U[bUjm + i]     + U[bUjj + i])     * 0.5f * (g_v[bV + jf * NX + imx] + vf);
    const float K1 = 0.5f * (U[bUjm + i + 1] + U[bUjj + i + 1]) * 0.5f * (vf + g_v[bV + jf * NX + ipx]);
    float rV = -(K1 - K0) / DXC;

    // y-advection: -delta_y( bar_y(pad_y(V)) * bar_y(pad_y(v)) )
    const float G0 = 0.5f * (VD + Vf) * 0.5f * (vD + vf);
    const float G1 = 0.5f * (Vf + VU) * 0.5f * (vf + vU);
    rV += -(G1 - G0) / DYC;

    // z-advection
    float H0 = 0.f, H1 = 0.f;
    if (k >= 1) {
        const int bo = (k - 1) * PC;
        const float Om = 0.5f * (g_Omega[bo + jm * NX + i] + g_Omega[bo + jj * NX + i]);
        const float vb = 0.5f * (g_v[bV - NYP * NX + jf * NX + i] + vf);
        H0 = Om * vb;
    }
    if (k < NZ - 1) {
        const int bo = k * PC;
        const float Om = 0.5f * (g_Omega[bo + jm * NX + i] + g_Omega[bo + jj * NX + i]);
        const float vb = 0.5f * (vf + g_v[bV + NYP * NX + jf * NX + i]);
        H1 = Om * vb;
    }
    rV += -(H1 - H0) / DZF;

    // pressure terms
    const int bcm = k * PC + jm * NX + i;
    const int bcj = k * PC + jj * NX + i;
    const float mufy  = 0.5f * (Mu[bcm]      + Mu[bcj]);
    const float alfy  = 0.5f * (g_alpha[bcm] + g_alpha[bcj]);
    const float dpy   = (g_p[bcj] - g_p[bcm]) / DYC;
    const float Py0   = 0.5f * (g_pzh[bcm]      + g_pzh[bcj]);
    const float Py1   = 0.5f * (g_pzh[bcm + PC] + g_pzh[bcj + PC]);
    const float dzP   = (Py1 - Py0) / DZF;
    const float dphiy = (g_Phih[bcj] - g_Phih[bcm]) / DYC;
    rV += -mufy * alfy * dpy - dzP * dphiy;

    const float c = (float)((double)read_dt(dtp) * coef);
    Vc[t] = V0[t] + c * rV;
}

// ---------------------------------------------------------------------------
// R_W and R_Phi fused: one thread per interface point (k=0..46, j, i)
// ---------------------------------------------------------------------------
__global__ __launch_bounds__(256)
void k_RWPhi(const float* __restrict__ U, const float* __restrict__ V,
             const float* __restrict__ Mu, const float* __restrict__ Phi,
             const float* __restrict__ W0, const float* __restrict__ P0,
             float* __restrict__ Wc, float* __restrict__ Pc,
             const void* __restrict__ dtp, double coef)
{
    int t = blockIdx.x * blockDim.x + threadIdx.x;
    if (t >= SZW) return;
    const int i = t % NX; const int r = t / NX;
    const int j = r % NY; const int k = r / NY;

    const int imx = (i == 0) ? NX - 1 : i - 1;
    const int ipx = (i == NX - 1) ? 0 : i + 1;
    const int jmy = (j == 0) ? NY - 1 : j - 1;
    const int jpy = (j == NY - 1) ? 0 : j + 1;

    const int bU0 = k * (NY * NXP) + j * NXP;
    const int bU1 = bU0 + NY * NXP;
    const int bV0 = k * (NYP * NX);
    const int bV1 = bV0 + NYP * NX;
    const int bw  = k * PC + j * NX;
    const float w0 = g_w[bw + i];

    // -delta_x( bar_z(U) * bar_x(pad_x(w)) )
    const float A0 = 0.5f * (U[bU0 + i]     + U[bU1 + i])     * 0.5f * (g_w[bw + imx] + w0);
    const float A1 = 0.5f * (U[bU0 + i + 1] + U[bU1 + i + 1]) * 0.5f * (w0 + g_w[bw + ipx]);
    float rW = -(A1 - A0) / DXC;

    // -delta_y( bar_z(V) * bar_y(pad_y(w)) )
    const float B0 = 0.5f * (V[bV0 + j       * NX + i] + V[bV1 + j       * NX + i]) * 0.5f * (g_w[k * PC + jmy * NX + i] + w0);
    const float B1 = 0.5f * (V[bV0 + (j + 1) * NX + i] + V[bV1 + (j + 1) * NX + i]) * 0.5f * (w0 + g_w[k * PC + jpy * NX + i]);
    rW += -(B1 - B0) / DYC;

    // -delta_z( bar_z(pad_z(Omega)) * bar_z(pad_z(w)) )
    const float OmB = g_Omega[bw + i];
    const float OmA = (k >= 1)       ? g_Omega[bw + i - PC] : 0.f;
    const float OmC = (k < NZW - 1)  ? g_Omega[bw + i + PC] : 0.f;
    const float wA  = (k >= 1)       ? g_w[bw + i - PC]     : 0.f;
    const float wC  = (k < NZW - 1)  ? g_w[bw + i + PC]     : 0.f;
    const float C0  = 0.5f * (OmA + OmB) * 0.5f * (wA + w0);
    const float C1  = 0.5f * (OmB + OmC) * 0.5f * (w0 + wC);
    rW += -(C1 - C0) / DZF;

    // buoyancy: G * (delta_z(p) - bar_z(Mu))
    const int bc0 = k * PC + j * NX;
    const int bc1 = bc0 + PC;
    rW += GRAV * ((g_p[bc1 + i] - g_p[bc0 + i]) / DZF - 0.5f * (Mu[bc0 + i] + Mu[bc1 + i]));

    // ---- R_Phi ----
    const float uzc = 0.5f * (0.5f * (g_u[bU0 + i] + g_u[bU0 + i + 1]) +
                              0.5f * (g_u[bU1 + i] + g_u[bU1 + i + 1]));
    const float dxPhi = (0.5f * (Phi[bw + i] + Phi[bw + ipx]) -
                         0.5f * (Phi[bw + imx] + Phi[bw + i])) / DXC;
    const float vzc = 0.5f * (0.5f * (g_v[bV0 + j * NX + i] + g_v[bV0 + (j + 1) * NX + i]) +
                              0.5f * (g_v[bV1 + j * NX + i] + g_v[bV1 + (j + 1) * NX + i]));
    const float dyPhi = (0.5f * (Phi[bw + i] + Phi[k * PC + jpy * NX + i]) -
                         0.5f * (Phi[k * PC + jmy * NX + i] + Phi[bw + i])) / DYC;
    float rP = -uzc * dxPhi - vzc * dyPhi
             - g_omega[bw + i] * (g_Phih[bc1 + i] - g_Phih[bc0 + i]) / DZF
             + GRAV * w0;

    const float c = (float)((double)read_dt(dtp) * coef);
    Wc[t] = W0[t] + c * rW;
    Pc[t] = P0[t] + c * rP;
}

// ---------------------------------------------------------------------------
// R_Theta and R_Mu fused: one thread per center (k, j, i)
// ---------------------------------------------------------------------------
__global__ __launch_bounds__(256)
void k_RTMu(const float* __restrict__ U, const float* __restrict__ V,
            const float* __restrict__ T0, const float* __restrict__ M0,
            float* __restrict__ Tc, float* __restrict__ Mc,
            const void* __restrict__ dtp, double coef)
{
    int t = blockIdx.x * blockDim.x + threadIdx.x;
    if (t >= SZC) return;
    const int i = t % NX; const int r = t / NX;
    const int j = r % NY; const int k = r / NY;

    const int imx = (i == 0) ? NX - 1 : i - 1;
    const int ipx = (i == NX - 1) ? 0 : i + 1;
    const int jmy = (j == 0) ? NY - 1 : j - 1;
    const int jpy = (j == NY - 1) ? 0 : j + 1;

    const int bU = k * (NY * NXP) + j * NXP;
    const int bV = k * (NYP * NX);
    const int bc = k * PC + j * NX;
    const float th0 = g_theta[bc + i];

    // Theta advection
    const float T0f = U[bU + i]     * 0.5f * (g_theta[bc + imx] + th0);
    const float T1f = U[bU + i + 1] * 0.5f * (th0 + g_theta[bc + ipx]);
    float rT = -(T1f - T0f) / DXC;

    const float S0 = V[bV + j       * NX + i] * 0.5f * (g_theta[k * PC + jmy * NX + i] + th0);
    const float S1 = V[bV + (j + 1) * NX + i] * 0.5f * (th0 + g_theta[k * PC + jpy * NX + i]);
    rT += -(S1 - S0) / DYC;

    float Z0 = 0.f, Z1 = 0.f;
    float OmD = 0.f, OmU = 0.f;
    if (k >= 1) {
        OmD = g_Omega[(k - 1) * PC + j * NX + i];
        Z0  = OmD * 0.5f * (g_theta[bc + i - PC] + th0);
    }
    if (k < NZ - 1) {
        OmU = g_Omega[k * PC + j * NX + i];
        Z1  = OmU * 0.5f * (th0 + g_theta[bc + i + PC]);
    }
    rT += -(Z1 - Z0) / DZF;

    // Mu continuity
    const float rM = -(U[bU + i + 1] - U[bU + i]) / DXC
                   - (V[bV + (j + 1) * NX + i] - V[bV + j * NX + i]) / DYC
                   - (OmU - OmD) / DZF;

    const float c = (float)((double)read_dt(dtp) * coef);
    Tc[t] = T0[t] + c * rT;
    Mc[t] = M0[t] + c * rM;
}

// ---------------------------------------------------------------------------
// Host launcher: 3 RK stages, 7 kernels each, all on the default stream.
// ---------------------------------------------------------------------------
extern "C" void kernel_launch(void* const* d_in, const int* in_sizes, int n_in,
                              void* d_out, int out_size)
{
    (void)in_sizes; (void)n_in; (void)out_size;
    const float* inU  = (const float*)d_in[0];
    const float* inV  = (const float*)d_in[1];
    const float* inW  = (const float*)d_in[2];
    const float* inT  = (const float*)d_in[3];
    const float* inM  = (const float*)d_in[4];
    const float* inP  = (const float*)d_in[5];
    const float* Phit = (const float*)d_in[6];
    const float* Phis = (const float*)d_in[7];
    const float* Pt   = (const float*)d_in[8];
    const float* Ps   = (const float*)d_in[9];
    const void*  dtp  = d_in[10];

    float *sU, *sV, *sW, *sT, *sM, *sP;
    cudaGetSymbolAddress((void**)&sU, g_sU);
    cudaGetSymbolAddress((void**)&sV, g_sV);
    cudaGetSymbolAddress((void**)&sW, g_sW);
    cudaGetSymbolAddress((void**)&sT, g_sT);
    cudaGetSymbolAddress((void**)&sM, g_sM);
    cudaGetSymbolAddress((void**)&sP, g_sP);

    float* out = (float*)d_out;
    float* oU = out;
    float* oV = oU + SZU;
    float* oW = oV + SZV;
    float* oT = oW + SZW;
    float* oM = oT + SZC;
    float* oP = oM + SZC;

    const double coefs[3] = {1.0 / 3.0, 1.0 / 2.0, 1.0};

    const float *cU = inU, *cV = inV, *cW = inW, *cT = inT, *cM = inM, *cP = inP;

    const int TB = 256;
    const int gCol = (PC  + TB - 1) / TB;
    const int gU   = (SZU + TB - 1) / TB;
    const int gV   = (SZV + TB - 1) / TB;
    const int gW   = (SZW + TB - 1) / TB;
    const int gC   = (SZC + TB - 1) / TB;

    for (int s = 0; s < 3; ++s) {
        float *dU, *dV, *dW, *dT, *dM, *dP;
        if (s < 2) {
            dU = sU + s * SZU; dV = sV + s * SZV; dW = sW + s * SZW;
            dT = sT + s * SZC; dM = sM + s * SZC; dP = sP + s * SZW;
        } else {
            dU = oU; dV = oV; dW = oW; dT = oT; dM = oM; dP = oP;
        }

        k_derive<<<gCol, TB>>>(cM, cT, cW, cP, Phit, Phis, Pt, Ps);
        k_derive_u<<<gU, TB>>>(cU, cM);
        k_derive_v<<<gV, TB>>>(cV, cM);
        k_RU   <<<gU, TB>>>(cU, cV, cM, inU, dU, dtp, coefs[s]);
        k_RV   <<<gV, TB>>>(cU, cV, cM, inV, dV, dtp, coefs[s]);
        k_RWPhi<<<gW, TB>>>(cU, cV, cM, cP, inW, inP, dW, dP, dtp, coefs[s]);
        k_RTMu <<<gC, TB>>>(cU, cV, inT, inM, dT, dM, dtp, coefs[s]);

        cU = dU; cV = dV; cW = dW; cT = dT; cM = dM; cP = dP;
    }
}

// round 2
// speedup vs baseline: 1.0007x; 1.0007x over previous
#include <cuda_runtime.h>
#include <cstdint>

// ---------------------------------------------------------------------------
// WRF RK3 step on GB (sm_100a). Pure stencil, HBM-bound.
// Grid: NZ=48 levels (cell centers), NY=NX=384 periodic in x,y.
// Staggering: U on x-faces (385), V on y-faces (385), W & Phi on 47 interior
// z-interfaces, Theta/Mu at centers.
// ---------------------------------------------------------------------------

constexpr int NX  = 384, NY = 384, NZ = 48;
constexpr int NXP = NX + 1;          // 385 x-faces
constexpr int NYP = NY + 1;          // 385 y-faces
constexpr int NZW = NZ - 1;          // 47 interior interfaces (W, Phi, Omega, w)
constexpr int NZI = NZ + 1;          // 49 interfaces (pzh)
constexpr int PC  = NX * NY;         // 147456 per-level plane
constexpr int SZC = NZ  * PC;        // 7,077,888  (Theta, Mu, p, alpha, theta, Phih)
constexpr int SZW = NZW * PC;        // 6,930,432  (W, Phi, Omega, omega, w)
constexpr int SZU = NZ * NY * NXP;   // 7,096,320
constexpr int SZV = NZ * NYP * NX;   // 7,096,320
constexpr int SZI = NZI * PC;        // 7,225,344  (pzh)

constexpr float PREF = 100000.0f;
constexpr float RDC  = 287.0f;
constexpr float GRAV = 9.81f;
constexpr float DXC  = 1000.0f;
constexpr float DYC  = 1000.0f;
#define DZF ((float)(1.0 / 49.0))

// Accurate f32 pow that bit-matches XLA's libdevice lowering regardless of
// -use_fast_math (under fast math, powf would become the inaccurate __powf).
#ifdef __FAST_MATH__
extern "C" __device__ float __nv_powf(float, float);
#define POWF(a, b) __nv_powf((a), (b))
#else
#define POWF(a, b) powf((a), (b))
#endif

// ---------------------------------------------------------------------------
// Scratch (static device globals; allocation is forbidden)
// ---------------------------------------------------------------------------
__device__ float g_sU[2 * SZU];
__device__ float g_sV[2 * SZV];
__device__ float g_sW[2 * SZW];
__device__ float g_sT[2 * SZC];
__device__ float g_sM[2 * SZC];
__device__ float g_sP[2 * SZW];

__device__ float g_p[SZC];        // pressure at centers
__device__ float g_alpha[SZC];    // specific volume
__device__ float g_theta[SZC];    // Theta / Mu
__device__ float g_Phih[SZC];     // bar_z(pad_z(Phi,Phi_t,Phi_s)) at centers
__device__ float g_pzh[SZI];      // bar_z(pad_z(p,P_t,P_s)) at 49 interfaces
__device__ float g_Omega[SZW];    // mass-weighted vertical velocity
__device__ float g_omega[SZW];
__device__ float g_w[SZW];        // W / bar_z(Mu)
__device__ float g_u[SZU];        // U / bar_x(pad_x(Mu))
__device__ float g_v[SZV];        // V / bar_y(pad_y(Mu))

__device__ __forceinline__ float read_dt(const void* p) {
    int iv = *(const int*)p;                 // int32 '4' -> 4 ; float 4.0 -> 0x40800000
    if (iv >= -1000000 && iv <= 1000000) return (float)iv;
    return *(const float*)p;
}

// ---------------------------------------------------------------------------
// Derive kernel: one thread per (i,j) column, streams k.
// Computes alpha, theta, p, Phih, pzh, Omega, omega, w for current state.
// ---------------------------------------------------------------------------
__global__ __launch_bounds__(256)
void k_derive(const float* __restrict__ Mu, const float* __restrict__ Th,
              const float* __restrict__ W,  const float* __restrict__ Phi,
              const float* __restrict__ Phit, const float* __restrict__ Phis,
              const float* __restrict__ Pt,   const float* __restrict__ Ps)
{
    int col = blockIdx.x * blockDim.x + threadIdx.x;
    if (col >= PC) return;
    const float pt = Pt[col], ps = Ps[col];
    float phi_lo = Phit[col];            // Phi_p[k]
    float a_prev = 0.f, p_prev = 0.f, m_prev = 0.f;
    for (int k = 0; k < NZ; ++k) {
        const int idx = k * PC + col;
        const float mu = Mu[idx];
        const float phi_hi = (k < NZW) ? Phi[k * PC + col] : Phis[col];  // Phi_p[k+1]
        // alpha = -delta_z(pad_z(Phi,Phi_t,Phi_s)) / Mu    (exact-rounded chain)
        const float dz  = __fdiv_rn(phi_hi - phi_lo, DZF);
        const float al  = __fdiv_rn(-dz, mu);
        const float th  = __fdiv_rn(Th[idx], mu);
        // x = RD*theta/PREF/alpha  (bit-exact vs reference: mul, div, div)
        const float x   = __fdiv_rn(__fdiv_rn(RDC * th, PREF), al);
        const float pk  = POWF(x, 1.4f) * PREF;
        g_alpha[idx] = al;
        g_theta[idx] = th;
        g_p[idx]     = pk;
        g_Phih[idx]  = 0.5f * (phi_lo + phi_hi);
        g_pzh[idx]   = 0.5f * ((k == 0 ? pt : p_prev) + pk);
        if (k > 0) {
            const int iw = (k - 1) * PC + col;
            const float bzm = 0.5f * (m_prev + mu);
            const float bza = 0.5f * (a_prev + al);
            const float wv  = __fdiv_rn(W[iw], bzm);
            const float om  = __fdiv_rn(__fdiv_rn(-wv * GRAV, bza), bzm);
            g_w[iw]     = wv;
            g_omega[iw] = om;
            g_Omega[iw] = om * bzm;
        }
        phi_lo = phi_hi; a_prev = al; p_prev = pk; m_prev = mu;
    }
    g_pzh[NZ * PC + col] = 0.5f * (p_prev + ps);
}

// u = U / bar_x(pad_x(Mu)) on the 385-face grid (periodic wrap)
__global__ __launch_bounds__(256)
void k_derive_u(const float* __restrict__ U, const float* __restrict__ Mu)
{
    int t = blockIdx.x * blockDim.x + threadIdx.x;
    if (t >= SZU) return;
    const int i = t % NXP; const int r = t / NXP;
    const int j = r % NY;  const int k = r / NY;
    const int ii = (i < NX) ? i : 0;
    const int im = (i == 0) ? NX - 1 : i - 1;
    const int bc = k * PC + j * NX;
    const float mf = 0.5f * (Mu[bc + im] + Mu[bc + ii]);
    g_u[t] = __fdiv_rn(U[t], mf);
}

// v = V / bar_y(pad_y(Mu)) on the 385-row grid
__global__ __launch_bounds__(256)
void k_derive_v(const float* __restrict__ V, const float* __restrict__ Mu)
{
    int t = blockIdx.x * blockDim.x + threadIdx.x;
    if (t >= SZV) return;
    const int i = t % NX;  const int r = t / NX;
    const int jf = r % NYP; const int k = r / NYP;
    const int jj = (jf < NY) ? jf : 0;
    const int jm = (jf == 0) ? NY - 1 : jf - 1;
    const float mf = 0.5f * (Mu[k * PC + jm * NX + i] + Mu[k * PC + jj * NX + i]);
    g_v[t] = __fdiv_rn(V[t], mf);
}

// ---------------------------------------------------------------------------
// R_U: one thread per U point (k, j, i-face)
// ---------------------------------------------------------------------------
__global__ __launch_bounds__(256)
void k_RU(const float* __restrict__ U, const float* __restrict__ V,
          const float* __restrict__ Mu,
          const float* __restrict__ U0, float* __restrict__ Uc,
          const void* __restrict__ dtp, double coef)
{
    int t = blockIdx.x * blockDim.x + threadIdx.x;
    if (t >= SZU) return;
    const int i = t % NXP; const int r = t / NXP;
    const int j = r % NY;  const int k = r / NY;

    const int ii = (i < NX) ? i : 0;
    const int im = (i == 0) ? NX - 1 : i - 1;
    const int fL = (i == 0) ? NXP - 1 : i - 1;     // padded face wrap
    const int fR = (i == NXP - 1) ? 0 : i + 1;
    const int jm = (j == 0) ? NY - 1 : j - 1;
    const int jp = (j == NY - 1) ? 0 : j + 1;

    const int bU  = k * (NY * NXP) + j * NXP;
    const float Uf = U[bU + i], UL = U[bU + fL], UR = U[bU + fR];
    const float uf = g_u[bU + i], uL = g_u[bU + fL], uR = g_u[bU + fR];

    // x-advection: -delta_x( bar_x(pad_x(U)) * bar_x(pad_x(u)) )
    const float F0 = 0.5f * (UL + Uf) * 0.5f * (uL + uf);
    const float F1 = 0.5f * (Uf + UR) * 0.5f * (uf + uR);
    float rU = -(F1 - F0) / DXC;

    // y-advection: -delta_y( bar_x(pad_x(V)) * bar_y(pad_y(u)) )
    const int bV = k * (NYP * NX);
    const float Va0 = 0.5f * (V[bV + j       * NX + im] + V[bV + j       * NX + ii]);
    const float Va1 = 0.5f * (V[bV + (j + 1) * NX + im] + V[bV + (j + 1) * NX + ii]);
    const float ub0 = 0.5f * (g_u[k * (NY * NXP) + jm * NXP + i] + uf);
    const float ub1 = 0.5f * (uf + g_u[k * (NY * NXP) + jp * NXP + i]);
    rU += -(Va1 * ub1 - Va0 * ub0) / DYC;

    // z-advection: -delta_z( bar_x(pad_x(pad_z(Omega))) * bar_z(pad_z(u)) )
    float H0 = 0.f, H1 = 0.f;
    if (k >= 1) {
        const int bo = (k - 1) * PC + j * NX;
        const float Om = 0.5f * (g_Omega[bo + im] + g_Omega[bo + ii]);
        const float ub = 0.5f * (g_u[bU - NY * NXP + i] + uf);
        H0 = Om * ub;
    }
    if (k < NZ - 1) {
        const int bo = k * PC + j * NX;
        const float Om = 0.5f * (g_Omega[bo + im] + g_Omega[bo + ii]);
        const float ub = 0.5f * (uf + g_u[bU + NY * NXP + i]);
        H1 = Om * ub;
    }
    rU += -(H1 - H0) / DZF;

    // pressure terms
    const int bc  = k * PC + j * NX;
    const int bc1 = bc + PC;
    const float mufx  = 0.5f * (Mu[bc + im]      + Mu[bc + ii]);
    const float alfx  = 0.5f * (g_alpha[bc + im] + g_alpha[bc + ii]);
    const float dpx   = (g_p[bc + ii] - g_p[bc + im]) / DXC;
    const float Px0   = 0.5f * (g_pzh[bc + im]  + g_pzh[bc + ii]);
    const float Px1   = 0.5f * (g_pzh[bc1 + im] + g_pzh[bc1 + ii]);
    const float dzP   = (Px1 - Px0) / DZF;
    const float dphix = (g_Phih[bc + ii] - g_Phih[bc + im]) / DXC;
    rU += -mufx * alfx * dpx - dzP * dphix;

    const float c = (float)((double)read_dt(dtp) * coef);
    Uc[t] = U0[t] + c * rU;
}

// ---------------------------------------------------------------------------
// R_V: one thread per V point (k, j-face, i)
// ---------------------------------------------------------------------------
__global__ __launch_bounds__(256)
void k_RV(const float* __restrict__ U, const float* __restrict__ V,
          const float* __restrict__ Mu,
          const float* __restrict__ V0, float* __restrict__ Vc,
          const void* __restrict__ dtp, double coef)
{
    int t = blockIdx.x * blockDim.x + threadIdx.x;
    if (t >= SZV) return;
    const int i  = t % NX;  const int r = t / NX;
    const int jf = r % NYP; const int k = r / NYP;

    const int jj = (jf < NY) ? jf : 0;
    const int jm = (jf == 0) ? NY - 1 : jf - 1;
    const int fD = (jf == 0) ? NYP - 1 : jf - 1;   // padded face wrap
    const int fU = (jf == NYP - 1) ? 0 : jf + 1;
    const int imx = (i == 0) ? NX - 1 : i - 1;
    const int ipx = (i == NX - 1) ? 0 : i + 1;

    const int bV = k * (NYP * NX);
    const float Vf = V[bV + jf * NX + i];
    const float VD = V[bV + fD * NX + i];
    const float VU = V[bV + fU * NX + i];
    const float vf = g_v[bV + jf * NX + i];
    const float vD = g_v[bV + fD * NX + i];
    const float vU = g_v[bV + fU * NX + i];

    // x-advection: -delta_x( bar_y(pad_y(U)) * bar_x(pad_x(v)) )
    const int bUjm = k * (NY * NXP) + jm * NXP;
    const int bUjj = k * (NY * NXP) + jj * NXP;
    const float K0 = 0.5f * (U[bUjm + i]     + U[bUjj + i])     * 0.5f * (g_v[bV + jf * NX + imx] + vf);
    const float K1 = 0.5f * (U[bUjm + i + 1] + U[bUjj + i + 1]) * 0.5f * (vf + g_v[bV + jf * NX + ipx]);
    float rV = -(K1 - K0) / DXC;

    // y-advection: -delta_y( bar_y(pad_y(V)) * bar_y(pad_y(v)) )
    const float G0 = 0.5f * (VD + Vf) * 0.5f * (vD + vf);
    const float G1 = 0.5f * (Vf + VU) * 0.5f * (vf + vU);
    rV += -(G1 - G0) / DYC;

    // z-advection
    float H0 = 0.f, H1 = 0.f;
    if (k >= 1) {
        const int bo = (k - 1) * PC;
        const float Om = 0.5f * (g_Omega[bo + jm * NX + i] + g_Omega[bo + jj * NX + i]);
        const float vb = 0.5f * (g_v[bV - NYP * NX + jf * NX + i] + vf);
        H0 = Om * vb;
    }
    if (k < NZ - 1) {
        const int bo = k * PC;
        const float Om = 0.5f * (g_Omega[bo + jm * NX + i] + g_Omega[bo + jj * NX + i]);
        const float vb = 0.5f * (vf + g_v[bV + NYP * NX + jf * NX + i]);
        H1 = Om * vb;
    }
    rV += -(H1 - H0) / DZF;

    // pressure terms
    const int bcm = k * PC + jm * NX + i;
    const int bcj = k * PC + jj * NX + i;
    const float mufy  = 0.5f * (Mu[bcm]      + Mu[bcj]);
    const float alfy  = 0.5f * (g_alpha[bcm] + g_alpha[bcj]);
    const float dpy   = (g_p[bcj] - g_p[bcm]) / DYC;
    const float Py0   = 0.5f * (g_pzh[bcm]      + g_pzh[bcj]);
    const float Py1   = 0.5f * (g_pzh[bcm + PC] + g_pzh[bcj + PC]);
    const float dzP   = (Py1 - Py0) / DZF;
    const float dphiy = (g_Phih[bcj] - g_Phih[bcm]) / DYC;
    rV += -mufy * alfy * dpy - dzP * dphiy;

    const float c = (float)((double)read_dt(dtp) * coef);
    Vc[t] = V0[t] + c * rV;
}

// ---------------------------------------------------------------------------
// R_W and R_Phi fused: one thread per interface point (k=0..46, j, i)
// ---------------------------------------------------------------------------
__global__ __launch_bounds__(256)
void k_RWPhi(const float* __restrict__ U, const float* __restrict__ V,
             const float* __restrict__ Mu, const float* __restrict__ Phi,
             const float* __restrict__ W0, const float* __restrict__ P0,
             float* __restrict__ Wc, float* __restrict__ Pc,
             const void* __restrict__ dtp, double coef)
{
    int t = blockIdx.x * blockDim.x + threadIdx.x;
    if (t >= SZW) return;
    const int i = t % NX; const int r = t / NX;
    const int j = r % NY; const int k = r / NY;

    const int imx = (i == 0) ? NX - 1 : i - 1;
    const int ipx = (i == NX - 1) ? 0 : i + 1;
    const int jmy = (j == 0) ? NY - 1 : j - 1;
    const int jpy = (j == NY - 1) ? 0 : j + 1;

    const int bU0 = k * (NY * NXP) + j * NXP;
    const int bU1 = bU0 + NY * NXP;
    const int bV0 = k * (NYP * NX);
    const int bV1 = bV0 + NYP * NX;
    const int bw  = k * PC + j * NX;
    const float w0 = g_w[bw + i];

    // -delta_x( bar_z(U) * bar_x(pad_x(w)) )
    const float A0 = 0.5f * (U[bU0 + i]     + U[bU1 + i])     * 0.5f * (g_w[bw + imx] + w0);
    const float A1 = 0.5f * (U[bU0 + i + 1] + U[bU1 + i + 1]) * 0.5f * (w0 + g_w[bw + ipx]);
    float rW = -(A1 - A0) / DXC;

    // -delta_y( bar_z(V) * bar_y(pad_y(w)) )
    const float B0 = 0.5f * (V[bV0 + j       * NX + i] + V[bV1 + j       * NX + i]) * 0.5f * (g_w[k * PC + jmy * NX + i] + w0);
    const float B1 = 0.5f * (V[bV0 + (j + 1) * NX + i] + V[bV1 + (j + 1) * NX + i]) * 0.5f * (w0 + g_w[k * PC + jpy * NX + i]);
    rW += -(B1 - B0) / DYC;

    // -delta_z( bar_z(pad_z(Omega)) * bar_z(pad_z(w)) )
    const float OmB = g_Omega[bw + i];
    const float OmA = (k >= 1)       ? g_Omega[bw + i - PC] : 0.f;
    const float OmC = (k < NZW - 1)  ? g_Omega[bw + i + PC] : 0.f;
    const float wA  = (k >= 1)       ? g_w[bw + i - PC]     : 0.f;
    const float wC  = (k < NZW - 1)  ? g_w[bw + i + PC]     : 0.f;
    const float C0  = 0.5f * (OmA + OmB) * 0.5f * (wA + w0);
    const float C1  = 0.5f * (OmB + OmC) * 0.5f * (w0 + wC);
    rW += -(C1 - C0) / DZF;

    // buoyancy: G * (delta_z(p) - bar_z(Mu))
    const int bc0 = k * PC + j * NX;
    const int bc1 = bc0 + PC;
    rW += GRAV * ((g_p[bc1 + i] - g_p[bc0 + i]) / DZF - 0.5f * (Mu[bc0 + i] + Mu[bc1 + i]));

    // ---- R_Phi ----
    const float uzc = 0.5f * (0.5f * (g_u[bU0 + i] + g_u[bU0 + i + 1]) +
                              0.5f * (g_u[bU1 + i] + g_u[bU1 + i + 1]));
    const float dxPhi = (0.5f * (Phi[bw + i] + Phi[bw + ipx]) -
                         0.5f * (Phi[bw + imx] + Phi[bw + i])) / DXC;
    const float vzc = 0.5f * (0.5f * (g_v[bV0 + j * NX + i] + g_v[bV0 + (j + 1) * NX + i]) +
                              0.5f * (g_v[bV1 + j * NX + i] + g_v[bV1 + (j + 1) * NX + i]));
    const float dyPhi = (0.5f * (Phi[bw + i] + Phi[k * PC + jpy * NX + i]) -
                         0.5f * (Phi[k * PC + jmy * NX + i] + Phi[bw + i])) / DYC;
    float rP = -uzc * dxPhi - vzc * dyPhi
             - g_omega[bw + i] * (g_Phih[bc1 + i] - g_Phih[bc0 + i]) / DZF
             + GRAV * w0;

    const float c = (float)((double)read_dt(dtp) * coef);
    Wc[t] = W0[t] + c * rW;
    Pc[t] = P0[t] + c * rP;
}

// ---------------------------------------------------------------------------
// R_Theta and R_Mu fused: one thread per center (k, j, i)
// ---------------------------------------------------------------------------
__global__ __launch_bounds__(256)
void k_RTMu(const float* __restrict__ U, const float* __restrict__ V,
            const float* __restrict__ T0, const float* __restrict__ M0,
            float* __restrict__ Tc, float* __restrict__ Mc,
            const void* __restrict__ dtp, double coef)
{
    int t = blockIdx.x * blockDim.x + threadIdx.x;
    if (t >= SZC) return;
    const int i = t % NX; const int r = t / NX;
    const int j = r % NY; const int k = r / NY;

    const int imx = (i == 0) ? NX - 1 : i - 1;
    const int ipx = (i == NX - 1) ? 0 : i + 1;
    const int jmy = (j == 0) ? NY - 1 : j - 1;
    const int jpy = (j == NY - 1) ? 0 : j + 1;

    const int bU = k * (NY * NXP) + j * NXP;
    const int bV = k * (NYP * NX);
    const int bc = k * PC + j * NX;
    const float th0 = g_theta[bc + i];

    // Theta advection
    const float T0f = U[bU + i]     * 0.5f * (g_theta[bc + imx] + th0);
    const float T1f = U[bU + i + 1] * 0.5f * (th0 + g_theta[bc + ipx]);
    float rT = -(T1f - T0f) / DXC;

    const float S0 = V[bV + j       * NX + i] * 0.5f * (g_theta[k * PC + jmy * NX + i] + th0);
    const float S1 = V[bV + (j + 1) * NX + i] * 0.5f * (th0 + g_theta[k * PC + jpy * NX + i]);
    rT += -(S1 - S0) / DYC;

    float Z0 = 0.f, Z1 = 0.f;
    float OmD = 0.f, OmU = 0.f;
    if (k >= 1) {
        OmD = g_Omega[(k - 1) * PC + j * NX + i];
        Z0  = OmD * 0.5f * (g_theta[bc + i - PC] + th0);
    }
    if (k < NZ - 1) {
        OmU = g_Omega[k * PC + j * NX + i];
        Z1  = OmU * 0.5f * (th0 + g_theta[bc + i + PC]);
    }
    rT += -(Z1 - Z0) / DZF;

    // Mu continuity
    const float rM = -(U[bU + i + 1] - U[bU + i]) / DXC
                   - (V[bV + (j + 1) * NX + i] - V[bV + j * NX + i]) / DYC
                   - (OmU - OmD) / DZF;

    const float c = (float)((double)read_dt(dtp) * coef);
    Tc[t] = T0[t] + c * rT;
    Mc[t] = M0[t] + c * rM;
}

// ---------------------------------------------------------------------------
// Host launcher: 3 RK stages, 7 kernels each, all on the default stream.
// ---------------------------------------------------------------------------
extern "C" void kernel_launch(void* const* d_in, const int* in_sizes, int n_in,
                              void* d_out, int out_size)
{
    (void)in_sizes; (void)n_in; (void)out_size;
    const float* inU  = (const float*)d_in[0];
    const float* inV  = (const float*)d_in[1];
    const float* inW  = (const float*)d_in[2];
    const float* inT  = (const float*)d_in[3];
    const float* inM  = (const float*)d_in[4];
    const float* inP  = (const float*)d_in[5];
    const float* Phit = (const float*)d_in[6];
    const float* Phis = (const float*)d_in[7];
    const float* Pt   = (const float*)d_in[8];
    const float* Ps   = (const float*)d_in[9];
    const void*  dtp  = d_in[10];

    float *sU, *sV, *sW, *sT, *sM, *sP;
    cudaGetSymbolAddress((void**)&sU, g_sU);
    cudaGetSymbolAddress((void**)&sV, g_sV);
    cudaGetSymbolAddress((void**)&sW, g_sW);
    cudaGetSymbolAddress((void**)&sT, g_sT);
    cudaGetSymbolAddress((void**)&sM, g_sM);
    cudaGetSymbolAddress((void**)&sP, g_sP);

    float* out = (float*)d_out;
    float* oU = out;
    float* oV = oU + SZU;
    float* oW = oV + SZV;
    float* oT = oW + SZW;
    float* oM = oT + SZC;
    float* oP = oM + SZC;

    const double coefs[3] = {1.0 / 3.0, 1.0 / 2.0, 1.0};

    const float *cU = inU, *cV = inV, *cW = inW, *cT = inT, *cM = inM, *cP = inP;

    const int TB = 256;
    const int gCol = (PC  + TB - 1) / TB;
    const int gU   = (SZU + TB - 1) / TB;
    const int gV   = (SZV + TB - 1) / TB;
    const int gW   = (SZW + TB - 1) / TB;
    const int gC   = (SZC + TB - 1) / TB;

    for (int s = 0; s < 3; ++s) {
        float *dU, *dV, *dW, *dT, *dM, *dP;
        if (s < 2) {
            dU = sU + s * SZU; dV = sV + s * SZV; dW = sW + s * SZW;
            dT = sT + s * SZC; dM = sM + s * SZC; dP = sP + s * SZW;
        } else {
            dU = oU; dV = oV; dW = oW; dT = oT; dM = oM; dP = oP;
        }

        k_derive<<<gCol, TB>>>(cM, cT, cW, cP, Phit, Phis, Pt, Ps);
        k_derive_u<<<gU, TB>>>(cU, cM);
        k_derive_v<<<gV, TB>>>(cV, cM);
        k_RU   <<<gU, TB>>>(cU, cV, cM, inU, dU, dtp, coefs[s]);
        k_RV   <<<gV, TB>>>(cU, cV, cM, inV, dV, dtp, coefs[s]);
        k_RWPhi<<<gW, TB>>>(cU, cV, cM, cP, inW, inP, dW, dP, dtp, coefs[s]);
        k_RTMu <<<gC, TB>>>(cU, cV, inT, inM, dT, dM, dtp, coefs[s]);

        cU = dU; cV = dV; cW = dW; cT = dT; cM = dM; cP = dP;
    }
}

// round 3
// speedup vs baseline: 1.1366x; 1.1359x over previous
#include <cuda_runtime.h>

constexpr int NX=384, NY=384, NZ=48;
constexpr int NXP=NX+1, NYP=NY+1, NZW=NZ-1;
constexpr int PC=NX*NY;
constexpr int SZC=NZ*PC, SZW=NZW*PC, SZU=NZ*NY*NXP, SZV=NZ*NYP*NX;
constexpr float PREF=100000.0f, RDC=287.0f, GRAV=9.81f, DXC=1000.0f, DYC=1000.0f;
#define DZF ((float)(1.0/49.0))

#ifdef __FAST_MATH__
extern "C" __device__ float __nv_powf(float,float);
#define POWF(a,b) __nv_powf((a),(b))
#else
#define POWF(a,b) powf((a),(b))
#endif

__device__ float g_sU[2*SZU]; __device__ float g_sV[2*SZV];
__device__ float g_sW[2*SZW]; __device__ float g_sT[2*SZC];
__device__ float g_sM[2*SZC]; __device__ float g_sP[2*SZW];

__device__ __forceinline__ float read_dt(const void* p){
    int iv=*(const int*)p;
    if(iv>=-1000000 && iv<=1000000) return (float)iv;
    return *(const float*)p;
}

constexpr int TX=32, TY=8, CW=34, CH=10, CS=CW*CH;

struct Smem {
    float mu[3][CS], al[3][CS], th[3][CS], p[3][CS], phih[3][CS];
    float u[3][CS], Ur[3][CS], v[3][CS], Vr[3][CS];
    float w[3][CS], Om[3][CS];
};

struct Ctx {
    const float *U,*V,*W,*Th,*Mu,*Phi,*Phit,*Phis,*Pt,*Ps;
};

// ---------------------------------------------------------------------------
__global__ __launch_bounds__(256)
void k_fused(Ctx c,
             const float* __restrict__ U0, const float* __restrict__ V0,
             const float* __restrict__ W0, const float* __restrict__ T0,
             const float* __restrict__ M0, const float* __restrict__ P0,
             float* __restrict__ Uc, float* __restrict__ Vc,
             float* __restrict__ Wc, float* __restrict__ Tc,
             float* __restrict__ Mc, float* __restrict__ PhiC,
             const void* __restrict__ dtp, double coef)
{
    __shared__ Smem sm;
    const int x0=blockIdx.x*TX, y0=blockIdx.y*TY;
    const int tid=threadIdx.x, tx=tid%TX, ty=tid/TX;
    const float cdt=(float)((double)read_dt(dtp)*coef);

    for(int L=0; L<=NZ; ++L){
        if(L<NZ){
            const int c3=L%3;
            for(int e=tid;e<CS;e+=256){
                int lx=e%CW, ly=e/CW;
                int gi=x0+lx-1; if(gi<0)gi+=NX; if(gi>=NX)gi-=NX;
                int gj=y0+ly-1; if(gj<0)gj+=NY; if(gj>=NY)gj-=NY;
                const int cc=gj*NX+gi;
                const float mu=c.Mu[L*PC+cc];
                const float f0=(L==0)?c.Phit[cc]:c.Phi[(L-1)*PC+cc];
                const float f1=(L==NZ-1)?c.Phis[cc]:c.Phi[L*PC+cc];
                const float dz=__fdiv_rn(f1-f0,DZF);
                const float al=__fdiv_rn(-dz,mu);
                const float th=__fdiv_rn(c.Th[L*PC+cc],mu);
                const float xv=__fdiv_rn(__fdiv_rn(RDC*th,PREF),al);
                sm.mu[c3][e]=mu; sm.al[c3][e]=al; sm.th[c3][e]=th;
                sm.p[c3][e]=POWF(xv,1.4f)*PREF;
                sm.phih[c3][e]=0.5f*(f0+f1);
            }
            for(int e=tid;e<CS;e+=256){
                int lx=e%CW, ly=e/CW;
                int ff=x0+lx-1; if(ff<0)ff=NXP-1;
                int gj=y0+ly-1; if(gj<0)gj+=NY; if(gj>=NY)gj-=NY;
                const int ci=(ff>=NX)?0:ff;
                const int im=(ci==0)?NX-1:ci-1;
                const float Uv=c.U[L*(NY*NXP)+gj*NXP+ff];
                const float mf=0.5f*(c.Mu[L*PC+gj*NX+im]+c.Mu[L*PC+gj*NX+ci]);
                sm.Ur[c3][e]=Uv; sm.u[c3][e]=__fdiv_rn(Uv,mf);
            }
            for(int e=tid;e<CS;e+=256){
                int lx=e%CW, ly=e/CW;
                int jf=y0+ly-1; if(jf<0)jf=NYP-1;
                int gi=x0+lx-1; if(gi<0)gi+=NX; if(gi>=NX)gi-=NX;
                const int cj=(jf>=NY)?0:jf;
                const int jm=(cj==0)?NY-1:cj-1;
                const float Vv=c.V[L*(NYP*NX)+jf*NX+gi];
                const float mf=0.5f*(c.Mu[L*PC+jm*NX+gi]+c.Mu[L*PC+cj*NX+gi]);
                sm.Vr[c3][e]=Vv; sm.v[c3][e]=__fdiv_rn(Vv,mf);
            }
        }
        __syncthreads();

        if(L>=1 && L<=NZW){
            const int kk=L-1, ib=kk%3, ia=(kk+1)%3;
            for(int e=tid;e<CS;e+=256){
                int lx=e%CW, ly=e/CW;
                int gi=x0+lx-1; if(gi<0)gi+=NX; if(gi>=NX)gi-=NX;
                int gj=y0+ly-1; if(gj<0)gj+=NY; if(gj>=NY)gj-=NY;
                const float bzm=0.5f*(sm.mu[ib][e]+sm.mu[ia][e]);
                const float bza=0.5f*(sm.al[ib][e]+sm.al[ia][e]);
                const float wv=__fdiv_rn(c.W[kk*PC+gj*NX+gi],bzm);
                const float om=__fdiv_rn(__fdiv_rn(-wv*GRAV,bza),bzm);
                sm.w[ib][e]=wv; sm.Om[ib][e]=om*bzm;
            }
        }
        __syncthreads();

        const int e0=(ty+1)*CW+(tx+1);
        const int eL=e0-1, eR=e0+1, eD=e0-CW, eU2=e0+CW;
        const int i=x0+tx, j=y0+ty;
        const int gim=(i==0)?NX-1:i-1;
        const int gjm=(j==0)?NY-1:j-1;

        if(L>=1){
            const int kc=L-1, c3=kc%3, cm=(kc+2)%3, cp=(kc+1)%3;
            {   // R_U at face i
                const float Uf=sm.Ur[c3][e0], ULf=sm.Ur[c3][eL], URf=sm.Ur[c3][eR];
                const float uf=sm.u[c3][e0], uL=sm.u[c3][eL], uR=sm.u[c3][eR];
                float rU=-(0.5f*(Uf+URf)*0.5f*(uf+uR)-0.5f*(ULf+Uf)*0.5f*(uL+uf))/DXC;
                const float Va0=0.5f*(sm.Vr[c3][eL]+sm.Vr[c3][e0]);
                const float Va1=0.5f*(sm.Vr[c3][eU2-1]+sm.Vr[c3][eU2]);
                rU+=-(Va1*0.5f*(uf+sm.u[c3][eU2])-Va0*0.5f*(sm.u[c3][eD]+uf))/DYC;
                float H0=0.f,H1=0.f;
                if(kc>=1) H0=0.5f*(sm.Om[cm][eL]+sm.Om[cm][e0])*0.5f*(sm.u[cm][e0]+uf);
                if(kc<NZ-1) H1=0.5f*(sm.Om[c3][eL]+sm.Om[c3][e0])*0.5f*(uf+sm.u[cp][e0]);
                rU+=-(H1-H0)/DZF;
                const float mufx=0.5f*(sm.mu[c3][eL]+sm.mu[c3][e0]);
                const float alfx=0.5f*(sm.al[c3][eL]+sm.al[c3][e0]);
                const float dpx=(sm.p[c3][e0]-sm.p[c3][eL])/DXC;
                const float pimA=(kc==0)?c.Pt[j*NX+gim]:sm.p[cm][eL];
                const float piiA=(kc==0)?c.Pt[j*NX+i]  :sm.p[cm][e0];
                const float pimB=(kc==NZ-1)?c.Ps[j*NX+gim]:sm.p[cp][eL];
                const float piiB=(kc==NZ-1)?c.Ps[j*NX+i]  :sm.p[cp][e0];
                const float Px0=0.5f*(0.5f*(pimA+sm.p[c3][eL])+0.5f*(piiA+sm.p[c3][e0]));
                const float Px1=0.5f*(0.5f*(sm.p[c3][eL]+pimB)+0.5f*(sm.p[c3][e0]+piiB));
                rU+=-mufx*alfx*dpx-((Px1-Px0)/DZF)*((sm.phih[c3][e0]-sm.phih[c3][eL])/DXC);
                const int o=kc*(NY*NXP)+j*NXP+i;
                Uc[o]=U0[o]+cdt*rU;
            }
            {   // R_V at row-face j
                const float Vf=sm.Vr[c3][e0], VD=sm.Vr[c3][eD], VU=sm.Vr[c3][eU2];
                const float vf=sm.v[c3][e0], vD=sm.v[c3][eD], vU=sm.v[c3][eU2];
                const float K0=0.5f*(sm.Ur[c3][eD]+sm.Ur[c3][e0])*0.5f*(sm.v[c3][eL]+vf);
                const float K1=0.5f*(sm.Ur[c3][eD+1]+sm.Ur[c3][eR])*0.5f*(vf+sm.v[c3][eR]);
                float rV=-(K1-K0)/DXC;
                rV+=-(0.5f*(Vf+VU)*0.5f*(vf+vU)-0.5f*(VD+Vf)*0.5f*(vD+vf))/DYC;
                float H0=0.f,H1=0.f;
                if(kc>=1) H0=0.5f*(sm.Om[cm][eD]+sm.Om[cm][e0])*0.5f*(sm.v[cm][e0]+vf);
                if(kc<NZ-1) H1=0.5f*(sm.Om[c3][eD]+sm.Om[c3][e0])*0.5f*(vf+sm.v[cp][e0]);
                rV+=-(H1-H0)/DZF;
                const float mufy=0.5f*(sm.mu[c3][eD]+sm.mu[c3][e0]);
                const float alfy=0.5f*(sm.al[c3][eD]+sm.al[c3][e0]);
                const float dpy=(sm.p[c3][e0]-sm.p[c3][eD])/DYC;
                const float pjmA=(kc==0)?c.Pt[gjm*NX+i]:sm.p[cm][eD];
                const float pjjA=(kc==0)?c.Pt[j*NX+i]  :sm.p[cm][e0];
                const float pjmB=(kc==NZ-1)?c.Ps[gjm*NX+i]:sm.p[cp][eD];
                const float pjjB=(kc==NZ-1)?c.Ps[j*NX+i]  :sm.p[cp][e0];
                const float Py0=0.5f*(0.5f*(pjmA+sm.p[c3][eD])+0.5f*(pjjA+sm.p[c3][e0]));
                const float Py1=0.5f*(0.5f*(sm.p[c3][eD]+pjmB)+0.5f*(sm.p[c3][e0]+pjjB));
                rV+=-mufy*alfy*dpy-((Py1-Py0)/DZF)*((sm.phih[c3][e0]-sm.phih[c3][eD])/DYC);
                const int o=kc*(NYP*NX)+j*NX+i;
                Vc[o]=V0[o]+cdt*rV;
            }
            {   // R_Theta / R_Mu
                const float th0=sm.th[c3][e0];
                float rT=-(sm.Ur[c3][eR]*0.5f*(th0+sm.th[c3][eR])
                          -sm.Ur[c3][e0]*0.5f*(sm.th[c3][eL]+th0))/DXC;
                rT+=-(sm.Vr[c3][eU2]*0.5f*(th0+sm.th[c3][eU2])
                     -sm.Vr[c3][e0]*0.5f*(sm.th[c3][eD]+th0))/DYC;
                float OmD=0.f,OmU=0.f,Z0=0.f,Z1=0.f;
                if(kc>=1){OmD=sm.Om[cm][e0]; Z0=OmD*0.5f*(sm.th[cm][e0]+th0);}
                if(kc<NZ-1){OmU=sm.Om[c3][e0]; Z1=OmU*0.5f*(th0+sm.th[cp][e0]);}
                rT+=-(Z1-Z0)/DZF;
                const float rM=-(sm.Ur[c3][eR]-sm.Ur[c3][e0])/DXC
                              -(sm.Vr[c3][eU2]-sm.Vr[c3][e0])/DYC
                              -(OmU-OmD)/DZF;
                const int o=kc*PC+j*NX+i;
                Tc[o]=T0[o]+cdt*rT;
                Mc[o]=M0[o]+cdt*rM;
            }
        }

        if(L>=2){
            const int ki=L-2, wi=ki%3, wm=(ki+2)%3, wp=(ki+1)%3;
            const int cA=ki%3, cB=(ki+1)%3;
            const float w0=sm.w[wi][e0];
            float rW=-(0.5f*(sm.Ur[cA][eR]+sm.Ur[cB][eR])*0.5f*(w0+sm.w[wi][eR])
                      -0.5f*(sm.Ur[cA][e0]+sm.Ur[cB][e0])*0.5f*(sm.w[wi][eL]+w0))/DXC;
            rW+=-(0.5f*(sm.Vr[cA][eU2]+sm.Vr[cB][eU2])*0.5f*(w0+sm.w[wi][eU2])
                 -0.5f*(sm.Vr[cA][e0]+sm.Vr[cB][e0])*0.5f*(sm.w[wi][eD]+w0))/DYC;
            const float OmB=sm.Om[wi][e0];
            const float OmA=(ki>=1)?sm.Om[wm][e0]:0.f;
            const float OmC=(ki<NZW-1)?sm.Om[wp][e0]:0.f;
            const float wA=(ki>=1)?sm.w[wm][e0]:0.f;
            const float wC=(ki<NZW-1)?sm.w[wp][e0]:0.f;
            rW+=-(0.5f*(OmB+OmC)*0.5f*(w0+wC)-0.5f*(OmA+OmB)*0.5f*(wA+w0))/DZF;
            rW+=GRAV*((sm.p[cB][e0]-sm.p[cA][e0])/DZF
                      -0.5f*(sm.mu[cA][e0]+sm.mu[cB][e0]));
            // R_Phi
            const int gip=(i==NX-1)?0:i+1;
            const int gjp=(j==NY-1)?0:j+1;
            const float Ph0=c.Phi[ki*PC+j*NX+i];
            const float PhL=c.Phi[ki*PC+j*NX+gim];
            const float PhR=c.Phi[ki*PC+j*NX+gip];
            const float PhD=c.Phi[ki*PC+gjm*NX+i];
            const float PhU=c.Phi[ki*PC+gjp*NX+i];
            const float uzc=0.5f*(0.5f*(sm.u[cA][e0]+sm.u[cA][eR])
                                 +0.5f*(sm.u[cB][e0]+sm.u[cB][eR]));
            const float vzc=0.5f*(0.5f*(sm.v[cA][e0]+sm.v[cA][eU2])
                                 +0.5f*(sm.v[cB][e0]+sm.v[cB][eU2]));
            const float dxPhi=(0.5f*(Ph0+PhR)-0.5f*(PhL+Ph0))/DXC;
            const float dyPhi=(0.5f*(Ph0+PhU)-0.5f*(PhD+Ph0))/DYC;
            const float bza=0.5f*(sm.al[cA][e0]+sm.al[cB][e0]);
            const float bzm=0.5f*(sm.mu[cA][e0]+sm.mu[cB][e0]);
            const float om=__fdiv_rn(__fdiv_rn(-w0*GRAV,bza),bzm);
            const float rP=-uzc*dxPhi-vzc*dyPhi
                          -om*(sm.phih[cB][e0]-sm.phih[cA][e0])/DZF+GRAV*w0;
            const int o=ki*PC+j*NX+i;
            Wc[o]=W0[o]+cdt*rW;
            PhiC[o]=P0[o]+cdt*rP;
        }
        __syncthreads();
    }
}

// ---------------- edge helpers (recompute derived quantities) --------------
__device__ __forceinline__ float e_alpha(const Ctx&c,int cc,int l){
    const float mu=c.Mu[l*PC+cc];
    const float f0=(l==0)?c.Phit[cc]:c.Phi[(l-1)*PC+cc];
    const float f1=(l==NZ-1)?c.Phis[cc]:c.Phi[l*PC+cc];
    return __fdiv_rn(-__fdiv_rn(f1-f0,DZF),mu);
}
__device__ __forceinline__ float e_press(const Ctx&c,int cc,int l){
    const float al=e_alpha(c,cc,l);
    const float th=__fdiv_rn(c.Th[l*PC+cc],c.Mu[l*PC+cc]);
    return POWF(__fdiv_rn(__fdiv_rn(RDC*th,PREF),al),1.4f)*PREF;
}
__device__ __forceinline__ float e_phih(const Ctx&c,int cc,int l){
    const float f0=(l==0)?c.Phit[cc]:c.Phi[(l-1)*PC+cc];
    const float f1=(l==NZ-1)?c.Phis[cc]:c.Phi[l*PC+cc];
    return 0.5f*(f0+f1);
}
__device__ __forceinline__ float e_pzh(const Ctx&c,int cc,int m){
    const float a=(m==0)?c.Pt[cc]:e_press(c,cc,m-1);
    const float b=(m==NZ)?c.Ps[cc]:e_press(c,cc,m);
    return 0.5f*(a+b);
}
__device__ __forceinline__ float e_Omg(const Ctx&c,int cc,int m){
    const float bzm=0.5f*(c.Mu[m*PC+cc]+c.Mu[(m+1)*PC+cc]);
    const float bza=0.5f*(e_alpha(c,cc,m)+e_alpha(c,cc,m+1));
    const float wv=__fdiv_rn(c.W[m*PC+cc],bzm);
    return __fdiv_rn(__fdiv_rn(-wv*GRAV,bza),bzm)*bzm;
}
__device__ __forceinline__ float e_u(const Ctx&c,int ff,int jj,int l){
    const int ci=(ff>=NX)?0:ff;
    const int im=(ci==0)?NX-1:ci-1;
    const float mf=0.5f*(c.Mu[l*PC+jj*NX+im]+c.Mu[l*PC+jj*NX+ci]);
    return __fdiv_rn(c.U[l*(NY*NXP)+jj*NXP+ff],mf);
}
__device__ __forceinline__ float e_v(const Ctx&c,int jf,int ii,int l){
    const int cj=(jf>=NY)?0:jf;
    const int jm=(cj==0)?NY-1:cj-1;
    const float mf=0.5f*(c.Mu[l*PC+jm*NX+ii]+c.Mu[l*PC+cj*NX+ii]);
    return __fdiv_rn(c.V[l*(NYP*NX)+jf*NX+ii],mf);
}

__global__ __launch_bounds__(256)
void k_edgeU(Ctx c, const float* __restrict__ U0, float* __restrict__ Uc,
             const void* __restrict__ dtp, double coef)
{
    int idx=blockIdx.x*blockDim.x+threadIdx.x;
    if(idx>=NZ*NY) return;
    const int k=idx/NY, j=idx%NY;
    const float cdt=(float)((double)read_dt(dtp)*coef);
    const int im=NX-1, ii=0, cim=j*NX+im, cii=j*NX+ii;
    const int bU=k*(NY*NXP)+j*NXP;
    const float Uf=c.U[bU+384], UL=c.U[bU+383], UR=c.U[bU+0];
    const float uf=e_u(c,384,j,k), uL=e_u(c,383,j,k), uR=e_u(c,0,j,k);
    float rU=-(0.5f*(Uf+UR)*0.5f*(uf+uR)-0.5f*(UL+Uf)*0.5f*(uL+uf))/DXC;
    const int jm=(j==0)?NY-1:j-1, jp=(j==NY-1)?0:j+1;
    const int bV=k*(NYP*NX);
    const float Va0=0.5f*(c.V[bV+j*NX+im]+c.V[bV+j*NX+ii]);
    const float Va1=0.5f*(c.V[bV+(j+1)*NX+im]+c.V[bV+(j+1)*NX+ii]);
    rU+=-(Va1*0.5f*(uf+e_u(c,384,jp,k))-Va0*0.5f*(e_u(c,384,jm,k)+uf))/DYC;
    float H0=0.f,H1=0.f;
    if(k>=1) H0=0.5f*(e_Omg(c,cim,k-1)+e_Omg(c,cii,k-1))*0.5f*(e_u(c,384,j,k-1)+uf);
    if(k<NZ-1) H1=0.5f*(e_Omg(c,cim,k)+e_Omg(c,cii,k))*0.5f*(uf+e_u(c,384,j,k+1));
    rU+=-(H1-H0)/DZF;
    const float mufx=0.5f*(c.Mu[k*PC+cim]+c.Mu[k*PC+cii]);
    const float alfx=0.5f*(e_alpha(c,cim,k)+e_alpha(c,cii,k));
    const float dpx=(e_press(c,cii,k)-e_press(c,cim,k))/DXC;
    const float Px0=0.5f*(e_pzh(c,cim,k)+e_pzh(c,cii,k));
    const float Px1=0.5f*(e_pzh(c,cim,k+1)+e_pzh(c,cii,k+1));
    rU+=-mufx*alfx*dpx-((Px1-Px0)/DZF)*((e_phih(c,cii,k)-e_phih(c,cim,k))/DXC);
    const int o=bU+384;
    Uc[o]=U0[o]+cdt*rU;
}

__global__ __launch_bounds__(256)
void k_edgeV(Ctx c, const float* __restrict__ V0, float* __restrict__ Vc,
             const void* __restrict__ dtp, double coef)
{
    int idx=blockIdx.x*blockDim.x+threadIdx.x;
    if(idx>=NZ*NX) return;
    const int k=idx/NX, i=idx%NX;
    const float cdt=(float)((double)read_dt(dtp)*coef);
    const int jm=NY-1, jj=0, cjm=jm*NX+i, cjj=jj*NX+i;
    const int bV=k*(NYP*NX);
    const float Vf=c.V[bV+384*NX+i], VD=c.V[bV+383*NX+i], VU=c.V[bV+0*NX+i];
    const float vf=e_v(c,384,i,k), vD=e_v(c,383,i,k), vU=e_v(c,0,i,k);
    const int imx=(i==0)?NX-1:i-1, ipx=(i==NX-1)?0:i+1;
    const int bU=k*(NY*NXP);
    const float K0=0.5f*(c.U[bU+jm*NXP+i]+c.U[bU+jj*NXP+i])*0.5f*(e_v(c,384,imx,k)+vf);
    const float K1=0.5f*(c.U[bU+jm*NXP+i+1]+c.U[bU+jj*NXP+i+1])*0.5f*(vf+e_v(c,384,ipx,k));
    float rV=-(K1-K0)/DXC;
    rV+=-(0.5f*(Vf+VU)*0.5f*(vf+vU)-0.5f*(VD+Vf)*0.5f*(vD+vf))/DYC;
    float H0=0.f,H1=0.f;
    if(k>=1) H0=0.5f*(e_Omg(c,cjm,k-1)+e_Omg(c,cjj,k-1))*0.5f*(e_v(c,384,i,k-1)+vf);
    if(k<NZ-1) H1=0.5f*(e_Omg(c,cjm,k)+e_Omg(c,cjj,k))*0.5f*(vf+e_v(c,384,i,k+1));
    rV+=-(H1-H0)/DZF;
    const float mufy=0.5f*(c.Mu[k*PC+cjm]+c.Mu[k*PC+cjj]);
    const float alfy=0.5f*(e_alpha(c,cjm,k)+e_alpha(c,cjj,k));
    const float dpy=(e_press(c,cjj,k)-e_press(c,cjm,k))/DYC;
    const float Py0=0.5f*(e_pzh(c,cjm,k)+e_pzh(c,cjj,k));
    const float Py1=0.5f*(e_pzh(c,cjm,k+1)+e_pzh(c,cjj,k+1));
    rV+=-mufy*alfy*dpy-((Py1-Py0)/DZF)*((e_phih(c,cjj,k)-e_phih(c,cjm,k))/DYC);
    const int o=bV+384*NX+i;
    Vc[o]=V0[o]+cdt*rV;
}

// ---------------------------------------------------------------------------
extern "C" void kernel_launch(void* const* d_in, const int* in_sizes, int n_in,
                              void* d_out, int out_size)
{
    (void)in_sizes;(void)n_in;(void)out_size;
    const float* inU=(const float*)d_in[0];
    const float* inV=(const float*)d_in[1];
    const float* inW=(const float*)d_in[2];
    const float* inT=(const float*)d_in[3];
    const float* inM=(const float*)d_in[4];
    const float* inP=(const float*)d_in[5];
    const float* Phit=(const float*)d_in[6];
    const float* Phis=(const float*)d_in[7];
    const float* Pt=(const float*)d_in[8];
    const float* Ps=(const float*)d_in[9];
    const void* dtp=d_in[10];

    float *sU,*sV,*sW,*sT,*sM,*sP;
    cudaGetSymbolAddress((void**)&sU,g_sU);
    cudaGetSymbolAddress((void**)&sV,g_sV);
    cudaGetSymbolAddress((void**)&sW,g_sW);
    cudaGetSymbolAddress((void**)&sT,g_sT);
    cudaGetSymbolAddress((void**)&sM,g_sM);
    cudaGetSymbolAddress((void**)&sP,g_sP);

    float* out=(float*)d_out;
    float* oU=out; float* oV=oU+SZU; float* oW=oV+SZV;
    float* oT=oW+SZW; float* oM=oT+SZC; float* oP=oM+SZC;

    const double coefs[3]={1.0/3.0, 1.0/2.0, 1.0};
    const float *cU=inU,*cV=inV,*cW=inW,*cT=inT,*cM=inM,*cP=inP;

    dim3 grid(NX/TX, NY/TY);
    const int gEU=(NZ*NY+255)/256, gEV=(NZ*NX+255)/256;

    for(int s=0;s<3;++s){
        float *dU,*dV,*dW,*dT,*dM,*dP;
        if(s<2){
            dU=sU+s*SZU; dV=sV+s*SZV; dW=sW+s*SZW;
            dT=sT+s*SZC; dM=sM+s*SZC; dP=sP+s*SZW;
        } else {
            dU=oU; dV=oV; dW=oW; dT=oT; dM=oM; dP=oP;
        }
        Ctx c{cU,cV,cW,cT,cM,cP,Phit,Phis,Pt,Ps};
        k_fused<<<grid,256>>>(c,inU,inV,inW,inT,inM,inP,
                              dU,dV,dW,dT,dM,dP,dtp,coefs[s]);
        k_edgeU<<<gEU,256>>>(c,inU,dU,dtp,coefs[s]);
        k_edgeV<<<gEV,256>>>(c,inV,dV,dtp,coefs[s]);
        cU=dU; cV=dV; cW=dW; cT=dT; cM=dM; cP=dP;
    }
}

// round 4
// speedup vs baseline: 1.3390x; 1.1781x over previous
#include <cuda_runtime.h>

constexpr int NX=384, NY=384, NZ=48;
constexpr int NXP=NX+1, NYP=NY+1, NZW=NZ-1;
constexpr int PC=NX*NY;
constexpr int SZC=NZ*PC, SZW=NZW*PC, SZU=NZ*NY*NXP, SZV=NZ*NYP*NX;
constexpr float PREF=100000.0f, RDC=287.0f, GRAV=9.81f, DXC=1000.0f, DYC=1000.0f;
#define DZF ((float)(1.0/49.0))

#ifdef __FAST_MATH__
extern "C" __device__ float __nv_powf(float,float);
#define POWF(a,b) __nv_powf((a),(b))
#else
#define POWF(a,b) powf((a),(b))
#endif

__device__ float g_sU[2*SZU]; __device__ float g_sV[2*SZV];
__device__ float g_sW[2*SZW]; __device__ float g_sT[2*SZC];
__device__ float g_sM[2*SZC]; __device__ float g_sP[2*SZW];

__device__ __forceinline__ float read_dt(const void* p){
    int iv=*(const int*)p;
    if(iv>=-1000000 && iv<=1000000) return (float)iv;
    return *(const float*)p;
}

constexpr int TX=32, TY=8, CW=34, CH=10, CS=CW*CH;

struct Smem {
    float mu[3][CS], th[3][CS], p[3][CS];
    float u[3][CS], Ur[3][CS], v[3][CS], Vr[3][CS];
    float w[3][CS], Om[3][CS];
    float fr[4][CS];            // raw Phi interface values, 4-deep by interface idx
};  // 31 slabs * 1360B = 42160 B

struct Ctx {
    const float *U,*V,*W,*Th,*Mu,*Phi,*Phit,*Phis,*Pt,*Ps;
};

// alpha / phih derived from raw interfaces (bit-identical rounding chains)
#define SM_AL(l,e) __fdiv_rn(-__fdiv_rn(sm.fr[((l)+1)&3][e]-sm.fr[(l)&3][e],DZF), sm.mu[(l)%3][e])
#define SM_PHIH(l,e) (0.5f*(sm.fr[(l)&3][e]+sm.fr[((l)+1)&3][e]))

__global__ __launch_bounds__(256,5)
void k_fused(Ctx c,
             const float* __restrict__ U0, const float* __restrict__ V0,
             const float* __restrict__ W0, const float* __restrict__ T0,
             const float* __restrict__ M0, const float* __restrict__ P0,
             float* __restrict__ Uc, float* __restrict__ Vc,
             float* __restrict__ Wc, float* __restrict__ Tc,
             float* __restrict__ Mc, float* __restrict__ PhiC,
             const void* __restrict__ dtp, double coef)
{
    __shared__ Smem sm;
    const int x0=blockIdx.x*TX, y0=blockIdx.y*TY;
    const int tid=threadIdx.x, tx=tid%TX, ty=tid/TX;
    const float cdt=(float)((double)read_dt(dtp)*coef);

    // Precompute per-thread slab-point indices (fixed across levels)
    int ccA[2], ffA[2], uimA[2], uciA[2], jfA[2], vjmA[2], vcjA[2], gjA[2], giA[2];
    #pragma unroll
    for(int ps=0; ps<2; ++ps){
        int e=tid+ps*256;
        if(e<CS){
            int lx=e%CW, ly=e/CW;
            int gi=x0+lx-1; if(gi<0)gi+=NX; if(gi>=NX)gi-=NX;
            int gj=y0+ly-1; if(gj<0)gj+=NY; if(gj>=NY)gj-=NY;
            ccA[ps]=gj*NX+gi; gjA[ps]=gj; giA[ps]=gi;
            int ff=x0+lx-1; if(ff<0)ff=NXP-1;
            ffA[ps]=ff;
            int uci=(ff>=NX)?0:ff;
            uciA[ps]=uci; uimA[ps]=(uci==0)?NX-1:uci-1;
            int jf=y0+ly-1; if(jf<0)jf=NYP-1;
            jfA[ps]=jf;
            int vcj=(jf>=NY)?0:jf;
            vcjA[ps]=vcj; vjmA[ps]=(vcj==0)?NY-1:vcj-1;
            // preload interface 0
            sm.fr[0][e]=c.Phit[ccA[ps]];
        }
    }

    for(int L=0; L<=NZ; ++L){
        if(L<NZ){
            const int c3=L%3, f4=(L+1)&3;
            #pragma unroll
            for(int ps=0; ps<2; ++ps){
                int e=tid+ps*256;
                if(e<CS){
                    const int cc=ccA[ps];
                    // ---- batched global loads ----
                    const float mu  = c.Mu[L*PC+cc];
                    const float thr = c.Th[L*PC+cc];
                    const float f1  = (L==NZ-1)? c.Phis[cc] : c.Phi[L*PC+cc];
                    const float Uv  = c.U[L*(NY*NXP)+gjA[ps]*NXP+ffA[ps]];
                    const float muA = c.Mu[L*PC+gjA[ps]*NX+uimA[ps]];
                    const float muB = c.Mu[L*PC+gjA[ps]*NX+uciA[ps]];
                    const float Vv  = c.V[L*(NYP*NX)+jfA[ps]*NX+giA[ps]];
                    const float muC = c.Mu[L*PC+vjmA[ps]*NX+giA[ps]];
                    const float muD = c.Mu[L*PC+vcjA[ps]*NX+giA[ps]];
                    float Wv=0.f;
                    if(L>=1) Wv=c.W[(L-1)*PC+cc];
                    // ---- compute + store ----
                    const float f0 = sm.fr[L&3][e];      // own-thread prior write
                    const float al = __fdiv_rn(-__fdiv_rn(f1-f0,DZF),mu);
                    const float th = __fdiv_rn(thr,mu);
                    const float xv = __fdiv_rn(__fdiv_rn(RDC*th,PREF),al);
                    sm.mu[c3][e]=mu; sm.th[c3][e]=th;
                    sm.p[c3][e]=POWF(xv,1.4f)*PREF;
                    sm.fr[f4][e]=f1;
                    sm.Ur[c3][e]=Uv; sm.u[c3][e]=__fdiv_rn(Uv,0.5f*(muA+muB));
                    sm.Vr[c3][e]=Vv; sm.v[c3][e]=__fdiv_rn(Vv,0.5f*(muC+muD));
                    if(L>=1){
                        const int pm=(L-1)%3;
                        const float muP=sm.mu[pm][e];    // own-thread
                        const float f0p=sm.fr[(L-1)&3][e];
                        const float alP=__fdiv_rn(-__fdiv_rn(f0-f0p,DZF),muP);
                        const float bzm=0.5f*(muP+mu);
                        const float bza=0.5f*(alP+al);
                        const float wv=__fdiv_rn(Wv,bzm);
                        const float om=__fdiv_rn(__fdiv_rn(-wv*GRAV,bza),bzm);
                        sm.w[pm][e]=wv; sm.Om[pm][e]=om*bzm;
                    }
                }
            }
        }
        __syncthreads();

        const int e0=(ty+1)*CW+(tx+1);
        const int eL=e0-1, eR=e0+1, eD=e0-CW, eU2=e0+CW;
        const int i=x0+tx, j=y0+ty;
        const int gim=(i==0)?NX-1:i-1;
        const int gjm=(j==0)?NY-1:j-1;

        if(L>=1){
            const int kc=L-1, c3=kc%3, cm=(kc+2)%3, cp=(kc+1)%3;
            {   // R_U
                const float Uf=sm.Ur[c3][e0], ULf=sm.Ur[c3][eL], URf=sm.Ur[c3][eR];
                const float uf=sm.u[c3][e0], uL=sm.u[c3][eL], uR=sm.u[c3][eR];
                float rU=-(0.5f*(Uf+URf)*0.5f*(uf+uR)-0.5f*(ULf+Uf)*0.5f*(uL+uf))/DXC;
                const float Va0=0.5f*(sm.Vr[c3][eL]+sm.Vr[c3][e0]);
                const float Va1=0.5f*(sm.Vr[c3][eU2-1]+sm.Vr[c3][eU2]);
                rU+=-(Va1*0.5f*(uf+sm.u[c3][eU2])-Va0*0.5f*(sm.u[c3][eD]+uf))/DYC;
                float H0=0.f,H1=0.f;
                if(kc>=1) H0=0.5f*(sm.Om[cm][eL]+sm.Om[cm][e0])*0.5f*(sm.u[cm][e0]+uf);
                if(kc<NZ-1) H1=0.5f*(sm.Om[c3][eL]+sm.Om[c3][e0])*0.5f*(uf+sm.u[cp][e0]);
                rU+=-(H1-H0)/DZF;
                const float mufx=0.5f*(sm.mu[c3][eL]+sm.mu[c3][e0]);
                const float alfx=0.5f*(SM_AL(kc,eL)+SM_AL(kc,e0));
                const float dpx=(sm.p[c3][e0]-sm.p[c3][eL])/DXC;
                const float pimA=(kc==0)?c.Pt[j*NX+gim]:sm.p[cm][eL];
                const float piiA=(kc==0)?c.Pt[j*NX+i]  :sm.p[cm][e0];
                const float pimB=(kc==NZ-1)?c.Ps[j*NX+gim]:sm.p[cp][eL];
                const float piiB=(kc==NZ-1)?c.Ps[j*NX+i]  :sm.p[cp][e0];
                const float Px0=0.5f*(0.5f*(pimA+sm.p[c3][eL])+0.5f*(piiA+sm.p[c3][e0]));
                const float Px1=0.5f*(0.5f*(sm.p[c3][eL]+pimB)+0.5f*(sm.p[c3][e0]+piiB));
                rU+=-mufx*alfx*dpx-((Px1-Px0)/DZF)*((SM_PHIH(kc,e0)-SM_PHIH(kc,eL))/DXC);
                const int o=kc*(NY*NXP)+j*NXP+i;
                Uc[o]=U0[o]+cdt*rU;
            }
            {   // R_V
                const float Vf=sm.Vr[c3][e0], VD=sm.Vr[c3][eD], VU=sm.Vr[c3][eU2];
                const float vf=sm.v[c3][e0], vD=sm.v[c3][eD], vU=sm.v[c3][eU2];
                const float K0=0.5f*(sm.Ur[c3][eD]+sm.Ur[c3][e0])*0.5f*(sm.v[c3][eL]+vf);
                const float K1=0.5f*(sm.Ur[c3][eD+1]+sm.Ur[c3][eR])*0.5f*(vf+sm.v[c3][eR]);
                float rV=-(K1-K0)/DXC;
                rV+=-(0.5f*(Vf+VU)*0.5f*(vf+vU)-0.5f*(VD+Vf)*0.5f*(vD+vf))/DYC;
                float H0=0.f,H1=0.f;
                if(kc>=1) H0=0.5f*(sm.Om[cm][eD]+sm.Om[cm][e0])*0.5f*(sm.v[cm][e0]+vf);
                if(kc<NZ-1) H1=0.5f*(sm.Om[c3][eD]+sm.Om[c3][e0])*0.5f*(vf+sm.v[cp][e0]);
                rV+=-(H1-H0)/DZF;
                const float mufy=0.5f*(sm.mu[c3][eD]+sm.mu[c3][e0]);
                const float alfy=0.5f*(SM_AL(kc,eD)+SM_AL(kc,e0));
                const float dpy=(sm.p[c3][e0]-sm.p[c3][eD])/DYC;
                const float pjmA=(kc==0)?c.Pt[gjm*NX+i]:sm.p[cm][eD];
                const float pjjA=(kc==0)?c.Pt[j*NX+i]  :sm.p[cm][e0];
                const float pjmB=(kc==NZ-1)?c.Ps[gjm*NX+i]:sm.p[cp][eD];
                const float pjjB=(kc==NZ-1)?c.Ps[j*NX+i]  :sm.p[cp][e0];
                const float Py0=0.5f*(0.5f*(pjmA+sm.p[c3][eD])+0.5f*(pjjA+sm.p[c3][e0]));
                const float Py1=0.5f*(0.5f*(sm.p[c3][eD]+pjmB)+0.5f*(sm.p[c3][e0]+pjjB));
                rV+=-mufy*alfy*dpy-((Py1-Py0)/DZF)*((SM_PHIH(kc,e0)-SM_PHIH(kc,eD))/DYC);
                const int o=kc*(NYP*NX)+j*NX+i;
                Vc[o]=V0[o]+cdt*rV;
            }
            {   // R_Theta / R_Mu
                const float th0=sm.th[c3][e0];
                float rT=-(sm.Ur[c3][eR]*0.5f*(th0+sm.th[c3][eR])
                          -sm.Ur[c3][e0]*0.5f*(sm.th[c3][eL]+th0))/DXC;
                rT+=-(sm.Vr[c3][eU2]*0.5f*(th0+sm.th[c3][eU2])
                     -sm.Vr[c3][e0]*0.5f*(sm.th[c3][eD]+th0))/DYC;
                float OmD=0.f,OmU=0.f,Z0=0.f,Z1=0.f;
                if(kc>=1){OmD=sm.Om[cm][e0]; Z0=OmD*0.5f*(sm.th[cm][e0]+th0);}
                if(kc<NZ-1){OmU=sm.Om[c3][e0]; Z1=OmU*0.5f*(th0+sm.th[cp][e0]);}
                rT+=-(Z1-Z0)/DZF;
                const float rM=-(sm.Ur[c3][eR]-sm.Ur[c3][e0])/DXC
                              -(sm.Vr[c3][eU2]-sm.Vr[c3][e0])/DYC
                              -(OmU-OmD)/DZF;
                const int o=kc*PC+j*NX+i;
                Tc[o]=T0[o]+cdt*rT;
                Mc[o]=M0[o]+cdt*rM;
            }
        }

        if(L>=2){
            const int ki=L-2, wi=ki%3, wm=(ki+2)%3, wp=(ki+1)%3;
            const int cA=ki%3, cB=(ki+1)%3;
            const float w0=sm.w[wi][e0];
            float rW=-(0.5f*(sm.Ur[cA][eR]+sm.Ur[cB][eR])*0.5f*(w0+sm.w[wi][eR])
                      -0.5f*(sm.Ur[cA][e0]+sm.Ur[cB][e0])*0.5f*(sm.w[wi][eL]+w0))/DXC;
            rW+=-(0.5f*(sm.Vr[cA][eU2]+sm.Vr[cB][eU2])*0.5f*(w0+sm.w[wi][eU2])
                 -0.5f*(sm.Vr[cA][e0]+sm.Vr[cB][e0])*0.5f*(sm.w[wi][eD]+w0))/DYC;
            const float OmB=sm.Om[wi][e0];
            const float OmA=(ki>=1)?sm.Om[wm][e0]:0.f;
            const float OmC=(ki<NZW-1)?sm.Om[wp][e0]:0.f;
            const float wA=(ki>=1)?sm.w[wm][e0]:0.f;
            const float wC=(ki<NZW-1)?sm.w[wp][e0]:0.f;
            rW+=-(0.5f*(OmB+OmC)*0.5f*(w0+wC)-0.5f*(OmA+OmB)*0.5f*(wA+w0))/DZF;
            rW+=GRAV*((sm.p[cB][e0]-sm.p[cA][e0])/DZF
                      -0.5f*(sm.mu[cA][e0]+sm.mu[cB][e0]));
            const int gip=(i==NX-1)?0:i+1;
            const int gjp=(j==NY-1)?0:j+1;
            const float Ph0=c.Phi[ki*PC+j*NX+i];
            const float PhL=c.Phi[ki*PC+j*NX+gim];
            const float PhR=c.Phi[ki*PC+j*NX+gip];
            const float PhD=c.Phi[ki*PC+gjm*NX+i];
            const float PhU=c.Phi[ki*PC+gjp*NX+i];
            const float uzc=0.5f*(0.5f*(sm.u[cA][e0]+sm.u[cA][eR])
                                 +0.5f*(sm.u[cB][e0]+sm.u[cB][eR]));
            const float vzc=0.5f*(0.5f*(sm.v[cA][e0]+sm.v[cA][eU2])
                                 +0.5f*(sm.v[cB][e0]+sm.v[cB][eU2]));
            const float dxPhi=(0.5f*(Ph0+PhR)-0.5f*(PhL+Ph0))/DXC;
            const float dyPhi=(0.5f*(Ph0+PhU)-0.5f*(PhD+Ph0))/DYC;
            const float bza=0.5f*(SM_AL(ki,e0)+SM_AL(ki+1,e0));
            const float bzm=0.5f*(sm.mu[cA][e0]+sm.mu[cB][e0]);
            const float om=__fdiv_rn(__fdiv_rn(-w0*GRAV,bza),bzm);
            const float rP=-uzc*dxPhi-vzc*dyPhi
                          -om*(SM_PHIH(ki+1,e0)-SM_PHIH(ki,e0))/DZF+GRAV*w0;
            const int o=ki*PC+j*NX+i;
            Wc[o]=W0[o]+cdt*rW;
            PhiC[o]=P0[o]+cdt*rP;
        }
        __syncthreads();
    }
}

// ---------------- edge helpers (recompute derived quantities) --------------
__device__ __forceinline__ float e_alpha(const Ctx&c,int cc,int l){
    const float mu=c.Mu[l*PC+cc];
    const float f0=(l==0)?c.Phit[cc]:c.Phi[(l-1)*PC+cc];
    const float f1=(l==NZ-1)?c.Phis[cc]:c.Phi[l*PC+cc];
    return __fdiv_rn(-__fdiv_rn(f1-f0,DZF),mu);
}
__device__ __forceinline__ float e_press(const Ctx&c,int cc,int l){
    const float al=e_alpha(c,cc,l);
    const float th=__fdiv_rn(c.Th[l*PC+cc],c.Mu[l*PC+cc]);
    return POWF(__fdiv_rn(__fdiv_rn(RDC*th,PREF),al),1.4f)*PREF;
}
__device__ __forceinline__ float e_phih(const Ctx&c,int cc,int l){
    const float f0=(l==0)?c.Phit[cc]:c.Phi[(l-1)*PC+cc];
    const float f1=(l==NZ-1)?c.Phis[cc]:c.Phi[l*PC+cc];
    return 0.5f*(f0+f1);
}
__device__ __forceinline__ float e_pzh(const Ctx&c,int cc,int m){
    const float a=(m==0)?c.Pt[cc]:e_press(c,cc,m-1);
    const float b=(m==NZ)?c.Ps[cc]:e_press(c,cc,m);
    return 0.5f*(a+b);
}
__device__ __forceinline__ float e_Omg(const Ctx&c,int cc,int m){
    const float bzm=0.5f*(c.Mu[m*PC+cc]+c.Mu[(m+1)*PC+cc]);
    const float bza=0.5f*(e_alpha(c,cc,m)+e_alpha(c,cc,m+1));
    const float wv=__fdiv_rn(c.W[m*PC+cc],bzm);
    return __fdiv_rn(__fdiv_rn(-wv*GRAV,bza),bzm)*bzm;
}
__device__ __forceinline__ float e_u(const Ctx&c,int ff,int jj,int l){
    const int ci=(ff>=NX)?0:ff;
    const int im=(ci==0)?NX-1:ci-1;
    const float mf=0.5f*(c.Mu[l*PC+jj*NX+im]+c.Mu[l*PC+jj*NX+ci]);
    return __fdiv_rn(c.U[l*(NY*NXP)+jj*NXP+ff],mf);
}
__device__ __forceinline__ float e_v(const Ctx&c,int jf,int ii,int l){
    const int cj=(jf>=NY)?0:jf;
    const int jm=(cj==0)?NY-1:cj-1;
    const float mf=0.5f*(c.Mu[l*PC+jm*NX+ii]+c.Mu[l*PC+cj*NX+ii]);
    return __fdiv_rn(c.V[l*(NYP*NX)+jf*NX+ii],mf);
}

__global__ __launch_bounds__(256)
void k_edgeU(Ctx c, const float* __restrict__ U0, float* __restrict__ Uc,
             const void* __restrict__ dtp, double coef)
{
    int idx=blockIdx.x*blockDim.x+threadIdx.x;
    if(idx>=NZ*NY) return;
    const int k=idx/NY, j=idx%NY;
    const float cdt=(float)((double)read_dt(dtp)*coef);
    const int im=NX-1, ii=0, cim=j*NX+im, cii=j*NX+ii;
    const int bU=k*(NY*NXP)+j*NXP;
    const float Uf=c.U[bU+384], UL=c.U[bU+383], UR=c.U[bU+0];
    const float uf=e_u(c,384,j,k), uL=e_u(c,383,j,k), uR=e_u(c,0,j,k);
    float rU=-(0.5f*(Uf+UR)*0.5f*(uf+uR)-0.5f*(UL+Uf)*0.5f*(uL+uf))/DXC;
    const int jm=(j==0)?NY-1:j-1, jp=(j==NY-1)?0:j+1;
    const int bV=k*(NYP*NX);
    const float Va0=0.5f*(c.V[bV+j*NX+im]+c.V[bV+j*NX+ii]);
    const float Va1=0.5f*(c.V[bV+(j+1)*NX+im]+c.V[bV+(j+1)*NX+ii]);
    rU+=-(Va1*0.5f*(uf+e_u(c,384,jp,k))-Va0*0.5f*(e_u(c,384,jm,k)+uf))/DYC;
    float H0=0.f,H1=0.f;
    if(k>=1) H0=0.5f*(e_Omg(c,cim,k-1)+e_Omg(c,cii,k-1))*0.5f*(e_u(c,384,j,k-1)+uf);
    if(k<NZ-1) H1=0.5f*(e_Omg(c,cim,k)+e_Omg(c,cii,k))*0.5f*(uf+e_u(c,384,j,k+1));
    rU+=-(H1-H0)/DZF;
    const float mufx=0.5f*(c.Mu[k*PC+cim]+c.Mu[k*PC+cii]);
    const float alfx=0.5f*(e_alpha(c,cim,k)+e_alpha(c,cii,k));
    const float dpx=(e_press(c,cii,k)-e_press(c,cim,k))/DXC;
    const float Px0=0.5f*(e_pzh(c,cim,k)+e_pzh(c,cii,k));
    const float Px1=0.5f*(e_pzh(c,cim,k+1)+e_pzh(c,cii,k+1));
    rU+=-mufx*alfx*dpx-((Px1-Px0)/DZF)*((e_phih(c,cii,k)-e_phih(c,cim,k))/DXC);
    const int o=bU+384;
    Uc[o]=U0[o]+cdt*rU;
}

__global__ __launch_bounds__(256)
void k_edgeV(Ctx c, const float* __restrict__ V0, float* __restrict__ Vc,
             const void* __restrict__ dtp, double coef)
{
    int idx=blockIdx.x*blockDim.x+threadIdx.x;
    if(idx>=NZ*NX) return;
    const int k=idx/NX, i=idx%NX;
    const float cdt=(float)((double)read_dt(dtp)*coef);
    const int jm=NY-1, jj=0, cjm=jm*NX+i, cjj=jj*NX+i;
    const int bV=k*(NYP*NX);
    const float Vf=c.V[bV+384*NX+i], VD=c.V[bV+383*NX+i], VU=c.V[bV+0*NX+i];
    const float vf=e_v(c,384,i,k), vD=e_v(c,383,i,k), vU=e_v(c,0,i,k);
    const int imx=(i==0)?NX-1:i-1, ipx=(i==NX-1)?0:i+1;
    const int bU=k*(NY*NXP);
    const float K0=0.5f*(c.U[bU+jm*NXP+i]+c.U[bU+jj*NXP+i])*0.5f*(e_v(c,384,imx,k)+vf);
    const float K1=0.5f*(c.U[bU+jm*NXP+i+1]+c.U[bU+jj*NXP+i+1])*0.5f*(vf+e_v(c,384,ipx,k));
    float rV=-(K1-K0)/DXC;
    rV+=-(0.5f*(Vf+VU)*0.5f*(vf+vU)-0.5f*(VD+Vf)*0.5f*(vD+vf))/DYC;
    float H0=0.f,H1=0.f;
    if(k>=1) H0=0.5f*(e_Omg(c,cjm,k-1)+e_Omg(c,cjj,k-1))*0.5f*(e_v(c,384,i,k-1)+vf);
    if(k<NZ-1) H1=0.5f*(e_Omg(c,cjm,k)+e_Omg(c,cjj,k))*0.5f*(vf+e_v(c,384,i,k+1));
    rV+=-(H1-H0)/DZF;
    const float mufy=0.5f*(c.Mu[k*PC+cjm]+c.Mu[k*PC+cjj]);
    const float alfy=0.5f*(e_alpha(c,cjm,k)+e_alpha(c,cjj,k));
    const float dpy=(e_press(c,cjj,k)-e_press(c,cjm,k))/DYC;
    const float Py0=0.5f*(e_pzh(c,cjm,k)+e_pzh(c,cjj,k));
    const float Py1=0.5f*(e_pzh(c,cjm,k+1)+e_pzh(c,cjj,k+1));
    rV+=-mufy*alfy*dpy-((Py1-Py0)/DZF)*((e_phih(c,cjj,k)-e_phih(c,cjm,k))/DYC);
    const int o=bV+384*NX+i;
    Vc[o]=V0[o]+cdt*rV;
}

// ---------------------------------------------------------------------------
extern "C" void kernel_launch(void* const* d_in, const int* in_sizes, int n_in,
                              void* d_out, int out_size)
{
    (void)in_sizes;(void)n_in;(void)out_size;
    const float* inU=(const float*)d_in[0];
    const float* inV=(const float*)d_in[1];
    const float* inW=(const float*)d_in[2];
    const float* inT=(const float*)d_in[3];
    const float* inM=(const float*)d_in[4];
    const float* inP=(const float*)d_in[5];
    const float* Phit=(const float*)d_in[6];
    const float* Phis=(const float*)d_in[7];
    const float* Pt=(const float*)d_in[8];
    const float* Ps=(const float*)d_in[9];
    const void* dtp=d_in[10];

    float *sU,*sV,*sW,*sT,*sM,*sP;
    cudaGetSymbolAddress((void**)&sU,g_sU);
    cudaGetSymbolAddress((void**)&sV,g_sV);
    cudaGetSymbolAddress((void**)&sW,g_sW);
    cudaGetSymbolAddress((void**)&sT,g_sT);
    cudaGetSymbolAddress((void**)&sM,g_sM);
    cudaGetSymbolAddress((void**)&sP,g_sP);

    float* out=(float*)d_out;
    float* oU=out; float* oV=oU+SZU; float* oW=oV+SZV;
    float* oT=oW+SZW; float* oM=oT+SZC; float* oP=oM+SZC;

    const double coefs[3]={1.0/3.0, 1.0/2.0, 1.0};
    const float *cU=inU,*cV=inV,*cW=inW,*cT=inT,*cM=inM,*cP=inP;

    dim3 grid(NX/TX, NY/TY);
    const int gEU=(NZ*NY+255)/256, gEV=(NZ*NX+255)/256;

    for(int s=0;s<3;++s){
        float *dU,*dV,*dW,*dT,*dM,*dP;
        if(s<2){
            dU=sU+s*SZU; dV=sV+s*SZV; dW=sW+s*SZW;
            dT=sT+s*SZC; dM=sM+s*SZC; dP=sP+s*SZW;
        } else {
            dU=oU; dV=oV; dW=oW; dT=oT; dM=oM; dP=oP;
        }
        Ctx c{cU,cV,cW,cT,cM,cP,Phit,Phis,Pt,Ps};
        k_fused<<<grid,256>>>(c,inU,inV,inW,inT,inM,inP,
                              dU,dV,dW,dT,dM,dP,dtp,coefs[s]);
        k_edgeU<<<gEU,256>>>(c,inU,dU,dtp,coefs[s]);
        k_edgeV<<<gEV,256>>>(c,inV,dV,dtp,coefs[s]);
        cU=dU; cV=dV; cW=dW; cT=dT; cM=dM; cP=dP;
    }
}

// round 5
// speedup vs baseline: 1.3785x; 1.0295x over previous
#include <cuda_runtime.h>

constexpr int NX=384, NY=384, NZ=48;
constexpr int NXP=NX+1, NYP=NY+1, NZW=NZ-1;
constexpr int PC=NX*NY;
constexpr int SZC=NZ*PC, SZW=NZW*PC, SZU=NZ*NY*NXP, SZV=NZ*NYP*NX;
constexpr float PREF=100000.0f, RDC=287.0f, GRAV=9.81f, DXC=1000.0f, DYC=1000.0f;
#define DZF ((float)(1.0/49.0))

#ifdef __FAST_MATH__
extern "C" __device__ float __nv_powf(float,float);
#define POWF(a,b) __nv_powf((a),(b))
#else
#define POWF(a,b) powf((a),(b))
#endif

__device__ float g_sU[2*SZU]; __device__ float g_sV[2*SZV];
__device__ float g_sW[2*SZW]; __device__ float g_sT[2*SZC];
__device__ float g_sM[2*SZC]; __device__ float g_sP[2*SZW];

__device__ __forceinline__ float read_dt(const void* p){
    int iv=*(const int*)p;
    if(iv>=-1000000 && iv<=1000000) return (float)iv;
    return *(const float*)p;
}

constexpr int TX=32, TY=8, CW=34, CH=10, CS=CW*CH;
constexpr int ZCH=12, NCHUNK=4;          // z-chunks per column

struct Smem {
    float mu[3][CS], th[3][CS], p[3][CS];
    float u[3][CS], Ur[3][CS], v[3][CS], Vr[3][CS];
    float w[3][CS], Om[3][CS];
    float fr[4][CS];            // raw interface (pad_z Phi) values, 4-deep
};

struct Ctx {
    const float *U,*V,*W,*Th,*Mu,*Phi,*Phit,*Phis,*Pt,*Ps;
};

#define SM_AL(l,e) __fdiv_rn(-__fdiv_rn(sm.fr[((l)+1)&3][e]-sm.fr[(l)&3][e],DZF), sm.mu[(l)%3][e])
#define SM_PHIH(l,e) (0.5f*(sm.fr[(l)&3][e]+sm.fr[((l)+1)&3][e]))

__global__ __launch_bounds__(256,5)
void k_fused(Ctx c,
             const float* __restrict__ U0, const float* __restrict__ V0,
             const float* __restrict__ W0, const float* __restrict__ T0,
             const float* __restrict__ M0, const float* __restrict__ P0,
             float* __restrict__ Uc, float* __restrict__ Vc,
             float* __restrict__ Wc, float* __restrict__ Tc,
             float* __restrict__ Mc, float* __restrict__ PhiC,
             const void* __restrict__ dtp, double coef)
{
    __shared__ Smem sm;
    const int x0=blockIdx.x*TX, y0=blockIdx.y*TY;
    const int c0=blockIdx.z*ZCH;                 // owned cells [c0, c1)
    const int c1=min(c0+ZCH, NZ);
    const int w1=min(c1, NZW);                   // owned interfaces [c0, w1)
    const int L0=max(c0-1, 0);
    const int Lend=min(c1+1, NZ);
    const int Lcap=min(c1+1, NZ-1);              // last level loaded
    const int tid=threadIdx.x, tx=tid%TX, ty=tid/TX;
    const float cdt=(float)((double)read_dt(dtp)*coef);

    int ccA[2], ffA[2], uimA[2], uciA[2], jfA[2], vjmA[2], vcjA[2], gjA[2], giA[2];
    #pragma unroll
    for(int ps=0; ps<2; ++ps){
        int e=tid+ps*256;
        if(e<CS){
            int lx=e%CW, ly=e/CW;
            int gi=x0+lx-1; if(gi<0)gi+=NX; if(gi>=NX)gi-=NX;
            int gj=y0+ly-1; if(gj<0)gj+=NY; if(gj>=NY)gj-=NY;
            ccA[ps]=gj*NX+gi; gjA[ps]=gj; giA[ps]=gi;
            int ff=x0+lx-1; if(ff<0)ff=NXP-1;
            ffA[ps]=ff;
            int uci=(ff>=NX)?0:ff;
            uciA[ps]=uci; uimA[ps]=(uci==0)?NX-1:uci-1;
            int jf=y0+ly-1; if(jf<0)jf=NYP-1;
            jfA[ps]=jf;
            int vcj=(jf>=NY)?0:jf;
            vcjA[ps]=vcj; vjmA[ps]=(vcj==0)?NY-1:vcj-1;
            // preload interface L0
            sm.fr[L0&3][e]=(L0==0)? c.Phit[ccA[ps]] : c.Phi[(L0-1)*PC+ccA[ps]];
        }
    }

    for(int L=L0; L<=Lend; ++L){
        if(L<=Lcap){
            const int c3=L%3, f4=(L+1)&3;
            #pragma unroll
            for(int ps=0; ps<2; ++ps){
                int e=tid+ps*256;
                if(e<CS){
                    const int cc=ccA[ps];
                    const float mu  = c.Mu[L*PC+cc];
                    const float thr = c.Th[L*PC+cc];
                    const float f1  = (L==NZ-1)? c.Phis[cc] : c.Phi[L*PC+cc];
                    const float Uv  = c.U[L*(NY*NXP)+gjA[ps]*NXP+ffA[ps]];
                    const float muA = c.Mu[L*PC+gjA[ps]*NX+uimA[ps]];
                    const float muB = c.Mu[L*PC+gjA[ps]*NX+uciA[ps]];
                    const float Vv  = c.V[L*(NYP*NX)+jfA[ps]*NX+giA[ps]];
                    const float muC = c.Mu[L*PC+vjmA[ps]*NX+giA[ps]];
                    const float muD = c.Mu[L*PC+vcjA[ps]*NX+giA[ps]];
                    float Wv=0.f;
                    if(L>L0) Wv=c.W[(L-1)*PC+cc];
                    const float f0 = sm.fr[L&3][e];
                    const float al = __fdiv_rn(-__fdiv_rn(f1-f0,DZF),mu);
                    const float th = __fdiv_rn(thr,mu);
                    const float xv = __fdiv_rn(__fdiv_rn(RDC*th,PREF),al);
                    sm.mu[c3][e]=mu; sm.th[c3][e]=th;
                    sm.p[c3][e]=POWF(xv,1.4f)*PREF;
                    sm.fr[f4][e]=f1;
                    sm.Ur[c3][e]=Uv; sm.u[c3][e]=__fdiv_rn(Uv,0.5f*(muA+muB));
                    sm.Vr[c3][e]=Vv; sm.v[c3][e]=__fdiv_rn(Vv,0.5f*(muC+muD));
                    if(L>L0){
                        const int pm=(L-1)%3;
                        const float muP=sm.mu[pm][e];
                        const float f0p=sm.fr[(L-1)&3][e];
                        const float alP=__fdiv_rn(-__fdiv_rn(f0-f0p,DZF),muP);
                        const float bzm=0.5f*(muP+mu);
                        const float bza=0.5f*(alP+al);
                        const float wv=__fdiv_rn(Wv,bzm);
                        const float om=__fdiv_rn(__fdiv_rn(-wv*GRAV,bza),bzm);
                        sm.w[pm][e]=wv; sm.Om[pm][e]=om*bzm;
                    }
                }
            }
        }
        __syncthreads();

        const int e0=(ty+1)*CW+(tx+1);
        const int eL=e0-1, eR=e0+1, eD=e0-CW, eU2=e0+CW;
        const int i=x0+tx, j=y0+ty;
        const int gim=(i==0)?NX-1:i-1;
        const int gjm=(j==0)?NY-1:j-1;

        const int kc=L-1;
        if(kc>=c0 && kc<c1){
            const int c3=kc%3, cm=(kc+2)%3, cp=(kc+1)%3;
            {   // R_U
                const float Uf=sm.Ur[c3][e0], ULf=sm.Ur[c3][eL], URf=sm.Ur[c3][eR];
                const float uf=sm.u[c3][e0], uL=sm.u[c3][eL], uR=sm.u[c3][eR];
                float rU=-(0.5f*(Uf+URf)*0.5f*(uf+uR)-0.5f*(ULf+Uf)*0.5f*(uL+uf))/DXC;
                const float Va0=0.5f*(sm.Vr[c3][eL]+sm.Vr[c3][e0]);
                const float Va1=0.5f*(sm.Vr[c3][eU2-1]+sm.Vr[c3][eU2]);
                rU+=-(Va1*0.5f*(uf+sm.u[c3][eU2])-Va0*0.5f*(sm.u[c3][eD]+uf))/DYC;
                float H0=0.f,H1=0.f;
                if(kc>=1) H0=0.5f*(sm.Om[cm][eL]+sm.Om[cm][e0])*0.5f*(sm.u[cm][e0]+uf);
                if(kc<NZ-1) H1=0.5f*(sm.Om[c3][eL]+sm.Om[c3][e0])*0.5f*(uf+sm.u[cp][e0]);
                rU+=-(H1-H0)/DZF;
                const float mufx=0.5f*(sm.mu[c3][eL]+sm.mu[c3][e0]);
                const float alfx=0.5f*(SM_AL(kc,eL)+SM_AL(kc,e0));
                const float dpx=(sm.p[c3][e0]-sm.p[c3][eL])/DXC;
                const float pimA=(kc==0)?c.Pt[j*NX+gim]:sm.p[cm][eL];
                const float piiA=(kc==0)?c.Pt[j*NX+i]  :sm.p[cm][e0];
                const float pimB=(kc==NZ-1)?c.Ps[j*NX+gim]:sm.p[cp][eL];
                const float piiB=(kc==NZ-1)?c.Ps[j*NX+i]  :sm.p[cp][e0];
                const float Px0=0.5f*(0.5f*(pimA+sm.p[c3][eL])+0.5f*(piiA+sm.p[c3][e0]));
                const float Px1=0.5f*(0.5f*(sm.p[c3][eL]+pimB)+0.5f*(sm.p[c3][e0]+piiB));
                rU+=-mufx*alfx*dpx-((Px1-Px0)/DZF)*((SM_PHIH(kc,e0)-SM_PHIH(kc,eL))/DXC);
                const int o=kc*(NY*NXP)+j*NXP+i;
                Uc[o]=U0[o]+cdt*rU;
            }
            {   // R_V
                const float Vf=sm.Vr[c3][e0], VD=sm.Vr[c3][eD], VU=sm.Vr[c3][eU2];
                const float vf=sm.v[c3][e0], vD=sm.v[c3][eD], vU=sm.v[c3][eU2];
                const float K0=0.5f*(sm.Ur[c3][eD]+sm.Ur[c3][e0])*0.5f*(sm.v[c3][eL]+vf);
                const float K1=0.5f*(sm.Ur[c3][eD+1]+sm.Ur[c3][eR])*0.5f*(vf+sm.v[c3][eR]);
                float rV=-(K1-K0)/DXC;
                rV+=-(0.5f*(Vf+VU)*0.5f*(vf+vU)-0.5f*(VD+Vf)*0.5f*(vD+vf))/DYC;
                float H0=0.f,H1=0.f;
                if(kc>=1) H0=0.5f*(sm.Om[cm][eD]+sm.Om[cm][e0])*0.5f*(sm.v[cm][e0]+vf);
                if(kc<NZ-1) H1=0.5f*(sm.Om[c3][eD]+sm.Om[c3][e0])*0.5f*(vf+sm.v[cp][e0]);
                rV+=-(H1-H0)/DZF;
                const float mufy=0.5f*(sm.mu[c3][eD]+sm.mu[c3][e0]);
                const float alfy=0.5f*(SM_AL(kc,eD)+SM_AL(kc,e0));
                const float dpy=(sm.p[c3][e0]-sm.p[c3][eD])/DYC;
                const float pjmA=(kc==0)?c.Pt[gjm*NX+i]:sm.p[cm][eD];
                const float pjjA=(kc==0)?c.Pt[j*NX+i]  :sm.p[cm][e0];
                const float pjmB=(kc==NZ-1)?c.Ps[gjm*NX+i]:sm.p[cp][eD];
                const float pjjB=(kc==NZ-1)?c.Ps[j*NX+i]  :sm.p[cp][e0];
                const float Py0=0.5f*(0.5f*(pjmA+sm.p[c3][eD])+0.5f*(pjjA+sm.p[c3][e0]));
                const float Py1=0.5f*(0.5f*(sm.p[c3][eD]+pjmB)+0.5f*(sm.p[c3][e0]+pjjB));
                rV+=-mufy*alfy*dpy-((Py1-Py0)/DZF)*((SM_PHIH(kc,e0)-SM_PHIH(kc,eD))/DYC);
                const int o=kc*(NYP*NX)+j*NX+i;
                Vc[o]=V0[o]+cdt*rV;
            }
            {   // R_Theta / R_Mu
                const float th0=sm.th[c3][e0];
                float rT=-(sm.Ur[c3][eR]*0.5f*(th0+sm.th[c3][eR])
                          -sm.Ur[c3][e0]*0.5f*(sm.th[c3][eL]+th0))/DXC;
                rT+=-(sm.Vr[c3][eU2]*0.5f*(th0+sm.th[c3][eU2])
                     -sm.Vr[c3][e0]*0.5f*(sm.th[c3][eD]+th0))/DYC;
                float OmD=0.f,OmU=0.f,Z0=0.f,Z1=0.f;
                if(kc>=1){OmD=sm.Om[cm][e0]; Z0=OmD*0.5f*(sm.th[cm][e0]+th0);}
                if(kc<NZ-1){OmU=sm.Om[c3][e0]; Z1=OmU*0.5f*(th0+sm.th[cp][e0]);}
                rT+=-(Z1-Z0)/DZF;
                const float rM=-(sm.Ur[c3][eR]-sm.Ur[c3][e0])/DXC
                              -(sm.Vr[c3][eU2]-sm.Vr[c3][e0])/DYC
                              -(OmU-OmD)/DZF;
                const int o=kc*PC+j*NX+i;
                Tc[o]=T0[o]+cdt*rT;
                Mc[o]=M0[o]+cdt*rM;
            }
        }

        const int ki=L-2;
        if(ki>=c0 && ki<w1){
            const int wi=ki%3, wm=(ki+2)%3, wp=(ki+1)%3;
            const int cA=ki%3, cB=(ki+1)%3;
            const float w0=sm.w[wi][e0];
            float rW=-(0.5f*(sm.Ur[cA][eR]+sm.Ur[cB][eR])*0.5f*(w0+sm.w[wi][eR])
                      -0.5f*(sm.Ur[cA][e0]+sm.Ur[cB][e0])*0.5f*(sm.w[wi][eL]+w0))/DXC;
            rW+=-(0.5f*(sm.Vr[cA][eU2]+sm.Vr[cB][eU2])*0.5f*(w0+sm.w[wi][eU2])
                 -0.5f*(sm.Vr[cA][e0]+sm.Vr[cB][e0])*0.5f*(sm.w[wi][eD]+w0))/DYC;
            const float OmB=sm.Om[wi][e0];
            const float OmA=(ki>=1)?sm.Om[wm][e0]:0.f;
            const float OmC=(ki<NZW-1)?sm.Om[wp][e0]:0.f;
            const float wA=(ki>=1)?sm.w[wm][e0]:0.f;
            const float wC=(ki<NZW-1)?sm.w[wp][e0]:0.f;
            rW+=-(0.5f*(OmB+OmC)*0.5f*(w0+wC)-0.5f*(OmA+OmB)*0.5f*(wA+w0))/DZF;
            rW+=GRAV*((sm.p[cB][e0]-sm.p[cA][e0])/DZF
                      -0.5f*(sm.mu[cA][e0]+sm.mu[cB][e0]));
            // R_Phi: Phi row ki == interface ki+1, in fr slab (bit-identical)
            const int fP=(ki+1)&3;
            const float Ph0=sm.fr[fP][e0];
            const float PhL=sm.fr[fP][eL];
            const float PhR=sm.fr[fP][eR];
            const float PhD=sm.fr[fP][eD];
            const float PhU=sm.fr[fP][eU2];
            const float uzc=0.5f*(0.5f*(sm.u[cA][e0]+sm.u[cA][eR])
                                 +0.5f*(sm.u[cB][e0]+sm.u[cB][eR]));
            const float vzc=0.5f*(0.5f*(sm.v[cA][e0]+sm.v[cA][eU2])
                                 +0.5f*(sm.v[cB][e0]+sm.v[cB][eU2]));
            const float dxPhi=(0.5f*(Ph0+PhR)-0.5f*(PhL+Ph0))/DXC;
            const float dyPhi=(0.5f*(Ph0+PhU)-0.5f*(PhD+Ph0))/DYC;
            const float bza=0.5f*(SM_AL(ki,e0)+SM_AL(ki+1,e0));
            const float bzm=0.5f*(sm.mu[cA][e0]+sm.mu[cB][e0]);
            const float om=__fdiv_rn(__fdiv_rn(-w0*GRAV,bza),bzm);
            const float rP=-uzc*dxPhi-vzc*dyPhi
                          -om*(SM_PHIH(ki+1,e0)-SM_PHIH(ki,e0))/DZF+GRAV*w0;
            const int o=ki*PC+j*NX+i;
            Wc[o]=W0[o]+cdt*rW;
            PhiC[o]=P0[o]+cdt*rP;
        }
        __syncthreads();
    }
}

// ---------------- edge helpers -------------------------------------------
__device__ __forceinline__ float e_alpha(const Ctx&c,int cc,int l){
    const float mu=c.Mu[l*PC+cc];
    const float f0=(l==0)?c.Phit[cc]:c.Phi[(l-1)*PC+cc];
    const float f1=(l==NZ-1)?c.Phis[cc]:c.Phi[l*PC+cc];
    return __fdiv_rn(-__fdiv_rn(f1-f0,DZF),mu);
}
__device__ __forceinline__ float e_press(const Ctx&c,int cc,int l){
    const float al=e_alpha(c,cc,l);
    const float th=__fdiv_rn(c.Th[l*PC+cc],c.Mu[l*PC+cc]);
    return POWF(__fdiv_rn(__fdiv_rn(RDC*th,PREF),al),1.4f)*PREF;
}
__device__ __forceinline__ float e_phih(const Ctx&c,int cc,int l){
    const float f0=(l==0)?c.Phit[cc]:c.Phi[(l-1)*PC+cc];
    const float f1=(l==NZ-1)?c.Phis[cc]:c.Phi[l*PC+cc];
    return 0.5f*(f0+f1);
}
__device__ __forceinline__ float e_pzh(const Ctx&c,int cc,int m){
    const float a=(m==0)?c.Pt[cc]:e_press(c,cc,m-1);
    const float b=(m==NZ)?c.Ps[cc]:e_press(c,cc,m);
    return 0.5f*(a+b);
}
__device__ __forceinline__ float e_Omg(const Ctx&c,int cc,int m){
    const float bzm=0.5f*(c.Mu[m*PC+cc]+c.Mu[(m+1)*PC+cc]);
    const float bza=0.5f*(e_alpha(c,cc,m)+e_alpha(c,cc,m+1));
    const float wv=__fdiv_rn(c.W[m*PC+cc],bzm);
    return __fdiv_rn(__fdiv_rn(-wv*GRAV,bza),bzm)*bzm;
}
__device__ __forceinline__ float e_u(const Ctx&c,int ff,int jj,int l){
    const int ci=(ff>=NX)?0:ff;
    const int im=(ci==0)?NX-1:ci-1;
    const float mf=0.5f*(c.Mu[l*PC+jj*NX+im]+c.Mu[l*PC+jj*NX+ci]);
    return __fdiv_rn(c.U[l*(NY*NXP)+jj*NXP+ff],mf);
}
__device__ __forceinline__ float e_v(const Ctx&c,int jf,int ii,int l){
    const int cj=(jf>=NY)?0:jf;
    const int jm=(cj==0)?NY-1:cj-1;
    const float mf=0.5f*(c.Mu[l*PC+jm*NX+ii]+c.Mu[l*PC+cj*NX+ii]);
    return __fdiv_rn(c.V[l*(NYP*NX)+jf*NX+ii],mf);
}

__global__ __launch_bounds__(256)
void k_edgeU(Ctx c, const float* __restrict__ U0, float* __restrict__ Uc,
             const void* __restrict__ dtp, double coef)
{
    int idx=blockIdx.x*blockDim.x+threadIdx.x;
    if(idx>=NZ*NY) return;
    const int k=idx/NY, j=idx%NY;
    const float cdt=(float)((double)read_dt(dtp)*coef);
    const int im=NX-1, ii=0, cim=j*NX+im, cii=j*NX+ii;
    const int bU=k*(NY*NXP)+j*NXP;
    const float Uf=c.U[bU+384], UL=c.U[bU+383], UR=c.U[bU+0];
    const float uf=e_u(c,384,j,k), uL=e_u(c,383,j,k), uR=e_u(c,0,j,k);
    float rU=-(0.5f*(Uf+UR)*0.5f*(uf+uR)-0.5f*(UL+Uf)*0.5f*(uL+uf))/DXC;
    const int jm=(j==0)?NY-1:j-1, jp=(j==NY-1)?0:j+1;
    const int bV=k*(NYP*NX);
    const float Va0=0.5f*(c.V[bV+j*NX+im]+c.V[bV+j*NX+ii]);
    const float Va1=0.5f*(c.V[bV+(j+1)*NX+im]+c.V[bV+(j+1)*NX+ii]);
    rU+=-(Va1*0.5f*(uf+e_u(c,384,jp,k))-Va0*0.5f*(e_u(c,384,jm,k)+uf))/DYC;
    float H0=0.f,H1=0.f;
    if(k>=1) H0=0.5f*(e_Omg(c,cim,k-1)+e_Omg(c,cii,k-1))*0.5f*(e_u(c,384,j,k-1)+uf);
    if(k<NZ-1) H1=0.5f*(e_Omg(c,cim,k)+e_Omg(c,cii,k))*0.5f*(uf+e_u(c,384,j,k+1));
    rU+=-(H1-H0)/DZF;
    const float mufx=0.5f*(c.Mu[k*PC+cim]+c.Mu[k*PC+cii]);
    const float alfx=0.5f*(e_alpha(c,cim,k)+e_alpha(c,cii,k));
    const float dpx=(e_press(c,cii,k)-e_press(c,cim,k))/DXC;
    const float Px0=0.5f*(e_pzh(c,cim,k)+e_pzh(c,cii,k));
    const float Px1=0.5f*(e_pzh(c,cim,k+1)+e_pzh(c,cii,k+1));
    rU+=-mufx*alfx*dpx-((Px1-Px0)/DZF)*((e_phih(c,cii,k)-e_phih(c,cim,k))/DXC);
    const int o=bU+384;
    Uc[o]=U0[o]+cdt*rU;
}

__global__ __launch_bounds__(256)
void k_edgeV(Ctx c, const float* __restrict__ V0, float* __restrict__ Vc,
             const void* __restrict__ dtp, double coef)
{
    int idx=blockIdx.x*blockDim.x+threadIdx.x;
    if(idx>=NZ*NX) return;
    const int k=idx/NX, i=idx%NX;
    const float cdt=(float)((double)read_dt(dtp)*coef);
    const int jm=NY-1, jj=0, cjm=jm*NX+i, cjj=jj*NX+i;
    const int bV=k*(NYP*NX);
    const float Vf=c.V[bV+384*NX+i], VD=c.V[bV+383*NX+i], VU=c.V[bV+0*NX+i];
    const float vf=e_v(c,384,i,k), vD=e_v(c,383,i,k), vU=e_v(c,0,i,k);
    const int imx=(i==0)?NX-1:i-1, ipx=(i==NX-1)?0:i+1;
    const int bU=k*(NY*NXP);
    const float K0=0.5f*(c.U[bU+jm*NXP+i]+c.U[bU+jj*NXP+i])*0.5f*(e_v(c,384,imx,k)+vf);
    const float K1=0.5f*(c.U[bU+jm*NXP+i+1]+c.U[bU+jj*NXP+i+1])*0.5f*(vf+e_v(c,384,ipx,k));
    float rV=-(K1-K0)/DXC;
    rV+=-(0.5f*(Vf+VU)*0.5f*(vf+vU)-0.5f*(VD+Vf)*0.5f*(vD+vf))/DYC;
    float H0=0.f,H1=0.f;
    if(k>=1) H0=0.5f*(e_Omg(c,cjm,k-1)+e_Omg(c,cjj,k-1))*0.5f*(e_v(c,384,i,k-1)+vf);
    if(k<NZ-1) H1=0.5f*(e_Omg(c,cjm,k)+e_Omg(c,cjj,k))*0.5f*(vf+e_v(c,384,i,k+1));
    rV+=-(H1-H0)/DZF;
    const float mufy=0.5f*(c.Mu[k*PC+cjm]+c.Mu[k*PC+cjj]);
    const float alfy=0.5f*(e_alpha(c,cjm,k)+e_alpha(c,cjj,k));
    const float dpy=(e_press(c,cjj,k)-e_press(c,cjm,k))/DYC;
    const float Py0=0.5f*(e_pzh(c,cjm,k)+e_pzh(c,cjj,k));
    const float Py1=0.5f*(e_pzh(c,cjm,k+1)+e_pzh(c,cjj,k+1));
    rV+=-mufy*alfy*dpy-((Py1-Py0)/DZF)*((e_phih(c,cjj,k)-e_phih(c,cjm,k))/DYC);
    const int o=bV+384*NX+i;
    Vc[o]=V0[o]+cdt*rV;
}

// ---------------------------------------------------------------------------
extern "C" void kernel_launch(void* const* d_in, const int* in_sizes, int n_in,
                              void* d_out, int out_size)
{
    (void)in_sizes;(void)n_in;(void)out_size;
    const float* inU=(const float*)d_in[0];
    const float* inV=(const float*)d_in[1];
    const float* inW=(const float*)d_in[2];
    const float* inT=(const float*)d_in[3];
    const float* inM=(const float*)d_in[4];
    const float* inP=(const float*)d_in[5];
    const float* Phit=(const float*)d_in[6];
    const float* Phis=(const float*)d_in[7];
    const float* Pt=(const float*)d_in[8];
    const float* Ps=(const float*)d_in[9];
    const void* dtp=d_in[10];

    float *sU,*sV,*sW,*sT,*sM,*sP;
    cudaGetSymbolAddress((void**)&sU,g_sU);
    cudaGetSymbolAddress((void**)&sV,g_sV);
    cudaGetSymbolAddress((void**)&sW,g_sW);
    cudaGetSymbolAddress((void**)&sT,g_sT);
    cudaGetSymbolAddress((void**)&sM,g_sM);
    cudaGetSymbolAddress((void**)&sP,g_sP);

    float* out=(float*)d_out;
    float* oU=out; float* oV=oU+SZU; float* oW=oV+SZV;
    float* oT=oW+SZW; float* oM=oT+SZC; float* oP=oM+SZC;

    const double coefs[3]={1.0/3.0, 1.0/2.0, 1.0};
    const float *cU=inU,*cV=inV,*cW=inW,*cT=inT,*cM=inM,*cP=inP;

    dim3 grid(NX/TX, NY/TY, NCHUNK);
    const int gEU=(NZ*NY+255)/256, gEV=(NZ*NX+255)/256;

    for(int s=0;s<3;++s){
        float *dU,*dV,*dW,*dT,*dM,*dP;
        if(s<2){
            dU=sU+s*SZU; dV=sV+s*SZV; dW=sW+s*SZW;
            dT=sT+s*SZC; dM=sM+s*SZC; dP=sP+s*SZW;
        } else {
            dU=oU; dV=oV; dW=oW; dT=oT; dM=oM; dP=oP;
        }
        Ctx c{cU,cV,cW,cT,cM,cP,Phit,Phis,Pt,Ps};
        k_fused<<<grid,256>>>(c,inU,inV,inW,inT,inM,inP,
                              dU,dV,dW,dT,dM,dP,dtp,coefs[s]);
        k_edgeU<<<gEU,256>>>(c,inU,dU,dtp,coefs[s]);
        k_edgeV<<<gEV,256>>>(c,inV,dV,dtp,coefs[s]);
        cU=dU; cV=dV; cW=dW; cT=dT; cM=dM; cP=dP;
    }
}

// round 7
// speedup vs baseline: 1.5559x; 1.1287x over previous
#include <cuda_runtime.h>

constexpr int NX=384, NY=384, NZ=48;
constexpr int NXP=NX+1, NYP=NY+1, NZW=NZ-1;
constexpr int PC=NX*NY;
constexpr int SZC=NZ*PC, SZW=NZW*PC, SZU=NZ*NY*NXP, SZV=NZ*NYP*NX;
constexpr float PREF=100000.0f, RDC=287.0f, GRAV=9.81f, DXC=1000.0f, DYC=1000.0f;
#define DZF ((float)(1.0/49.0))

#ifdef __FAST_MATH__
extern "C" __device__ float __nv_powf(float,float);
#define POWF(a,b) __nv_powf((a),(b))
#else
#define POWF(a,b) powf((a),(b))
#endif

__device__ float g_sU[2*SZU]; __device__ float g_sV[2*SZV];
__device__ float g_sW[2*SZW]; __device__ float g_sT[2*SZC];
__device__ float g_sM[2*SZC]; __device__ float g_sP[2*SZW];

__device__ __forceinline__ float read_dt(const void* p){
    int iv=*(const int*)p;
    if(iv>=-1000000 && iv<=1000000) return (float)iv;
    return *(const float*)p;
}

constexpr int TX=32, TY=8, CW=34, CH=10, CS=CW*CH;
constexpr int ZCH=12, NCHUNK=4;

struct Smem {
    float mu[3][CS], al[3][CS], th[3][CS], p[3][CS];
    float u[3][CS], Ur[3][CS], v[3][CS], Vr[3][CS];
    float w[3][CS], Om[3][CS];
    float fr[4][CS];            // raw interface (pad_z Phi) values, 4-deep
};  // 34 slabs * 1360B = 46240 B -> 4 blocks/SM

struct Ctx {
    const float *U,*V,*W,*Th,*Mu,*Phi,*Phit,*Phis,*Pt,*Ps;
};

#define SM_PHIH(l,e) (0.5f*(sm.fr[(l)&3][e]+sm.fr[((l)+1)&3][e]))

__global__ __launch_bounds__(256,4)
void k_fused(Ctx c,
             const float* __restrict__ U0, const float* __restrict__ V0,
             const float* __restrict__ W0, const float* __restrict__ T0,
             const float* __restrict__ M0, const float* __restrict__ P0,
             float* __restrict__ Uc, float* __restrict__ Vc,
             float* __restrict__ Wc, float* __restrict__ Tc,
             float* __restrict__ Mc, float* __restrict__ PhiC,
             const void* __restrict__ dtp, double coef)
{
    __shared__ Smem sm;
    const int x0=blockIdx.x*TX, y0=blockIdx.y*TY;
    const int c0=blockIdx.z*ZCH;
    const int c1=min(c0+ZCH, NZ);
    const int w1=min(c1, NZW);
    const int L0=max(c0-1, 0);
    const int Lend=min(c1+1, NZ);
    const int Lcap=min(c1+1, NZ-1);
    const int tid=threadIdx.x, tx=tid%TX, ty=tid/TX;
    const float cdt=(float)((double)read_dt(dtp)*coef);

    int ccA[2], ffA[2], uimA[2], uciA[2], jfA[2], vjmA[2], vcjA[2], gjA[2], giA[2];
    #pragma unroll
    for(int ps=0; ps<2; ++ps){
        int e=tid+ps*256;
        if(e<CS){
            int lx=e%CW, ly=e/CW;
            int gi=x0+lx-1; if(gi<0)gi+=NX; if(gi>=NX)gi-=NX;
            int gj=y0+ly-1; if(gj<0)gj+=NY; if(gj>=NY)gj-=NY;
            ccA[ps]=gj*NX+gi; gjA[ps]=gj; giA[ps]=gi;
            int ff=x0+lx-1; if(ff<0)ff=NXP-1;
            ffA[ps]=ff;
            int uci=(ff>=NX)?0:ff;
            uciA[ps]=uci; uimA[ps]=(uci==0)?NX-1:uci-1;
            int jf=y0+ly-1; if(jf<0)jf=NYP-1;
            jfA[ps]=jf;
            int vcj=(jf>=NY)?0:jf;
            vcjA[ps]=vcj; vjmA[ps]=(vcj==0)?NY-1:vcj-1;
            sm.fr[L0&3][e]=(L0==0)? c.Phit[ccA[ps]] : c.Phi[(L0-1)*PC+ccA[ps]];
        }
    }

    for(int L=L0; L<=Lend; ++L){
        if(L<=Lcap){
            const int c3=L%3, f4=(L+1)&3;
            #pragma unroll
            for(int ps=0; ps<2; ++ps){
                int e=tid+ps*256;
                if(e<CS){
                    const int cc=ccA[ps];
                    const float mu  = c.Mu[L*PC+cc];
                    const float thr = c.Th[L*PC+cc];
                    const float f1  = (L==NZ-1)? c.Phis[cc] : c.Phi[L*PC+cc];
                    const float Uv  = c.U[L*(NY*NXP)+gjA[ps]*NXP+ffA[ps]];
                    const float muA = c.Mu[L*PC+gjA[ps]*NX+uimA[ps]];
                    const float muB = c.Mu[L*PC+gjA[ps]*NX+uciA[ps]];
                    const float Vv  = c.V[L*(NYP*NX)+jfA[ps]*NX+giA[ps]];
                    const float muC = c.Mu[L*PC+vjmA[ps]*NX+giA[ps]];
                    const float muD = c.Mu[L*PC+vcjA[ps]*NX+giA[ps]];
                    float Wv=0.f;
                    if(L>L0) Wv=c.W[(L-1)*PC+cc];
                    const float f0 = sm.fr[L&3][e];
                    // exact chain (feeds pow -> pressure; amplified by /DZ later)
                    const float al = __fdiv_rn(-__fdiv_rn(f1-f0,DZF),mu);
                    const float th = __fdiv_rn(thr,mu);
                    const float xv = __fdiv_rn(__fdiv_rn(RDC*th,PREF),al);
                    sm.mu[c3][e]=mu; sm.al[c3][e]=al; sm.th[c3][e]=th;
                    sm.p[c3][e]=POWF(xv,1.4f)*PREF;
                    sm.fr[f4][e]=f1;
                    // fast divides (advection-only paths)
                    sm.Ur[c3][e]=Uv; sm.u[c3][e]=__fdividef(Uv,0.5f*(muA+muB));
                    sm.Vr[c3][e]=Vv; sm.v[c3][e]=__fdividef(Vv,0.5f*(muC+muD));
                    if(L>L0){
                        const int pm=(L-1)%3;
                        const float bzm=0.5f*(sm.mu[pm][e]+mu);
                        const float bza=0.5f*(sm.al[pm][e]+al);
                        const float wv=__fdividef(Wv,bzm);
                        const float om=__fdividef(__fdividef(-wv*GRAV,bza),bzm);
                        sm.w[pm][e]=wv; sm.Om[pm][e]=om*bzm;
                    }
                }
            }
        }
        __syncthreads();

        const int e0=(ty+1)*CW+(tx+1);
        const int eL=e0-1, eR=e0+1, eD=e0-CW, eU2=e0+CW;
        const int i=x0+tx, j=y0+ty;
        const int gim=(i==0)?NX-1:i-1;
        const int gjm=(j==0)?NY-1:j-1;

        const int kc=L-1;
        if(kc>=c0 && kc<c1){
            const int c3=kc%3, cm=(kc+2)%3, cp=(kc+1)%3;
            {   // R_U
                const float Uf=sm.Ur[c3][e0], ULf=sm.Ur[c3][eL], URf=sm.Ur[c3][eR];
                const float uf=sm.u[c3][e0], uL=sm.u[c3][eL], uR=sm.u[c3][eR];
                float rU=-(0.5f*(Uf+URf)*0.5f*(uf+uR)-0.5f*(ULf+Uf)*0.5f*(uL+uf))/DXC;
                const float Va0=0.5f*(sm.Vr[c3][eL]+sm.Vr[c3][e0]);
                const float Va1=0.5f*(sm.Vr[c3][eU2-1]+sm.Vr[c3][eU2]);
                rU+=-(Va1*0.5f*(uf+sm.u[c3][eU2])-Va0*0.5f*(sm.u[c3][eD]+uf))/DYC;
                float H0=0.f,H1=0.f;
                if(kc>=1) H0=0.5f*(sm.Om[cm][eL]+sm.Om[cm][e0])*0.5f*(sm.u[cm][e0]+uf);
                if(kc<NZ-1) H1=0.5f*(sm.Om[c3][eL]+sm.Om[c3][e0])*0.5f*(uf+sm.u[cp][e0]);
                rU+=-(H1-H0)/DZF;
                const float mufx=0.5f*(sm.mu[c3][eL]+sm.mu[c3][e0]);
                const float alfx=0.5f*(sm.al[c3][eL]+sm.al[c3][e0]);
                const float dpx=(sm.p[c3][e0]-sm.p[c3][eL])/DXC;
                const float pimA=(kc==0)?c.Pt[j*NX+gim]:sm.p[cm][eL];
                const float piiA=(kc==0)?c.Pt[j*NX+i]  :sm.p[cm][e0];
                const float pimB=(kc==NZ-1)?c.Ps[j*NX+gim]:sm.p[cp][eL];
                const float piiB=(kc==NZ-1)?c.Ps[j*NX+i]  :sm.p[cp][e0];
                const float Px0=0.5f*(0.5f*(pimA+sm.p[c3][eL])+0.5f*(piiA+sm.p[c3][e0]));
                const float Px1=0.5f*(0.5f*(sm.p[c3][eL]+pimB)+0.5f*(sm.p[c3][e0]+piiB));
                rU+=-mufx*alfx*dpx-((Px1-Px0)/DZF)*((SM_PHIH(kc,e0)-SM_PHIH(kc,eL))/DXC);
                const int o=kc*(NY*NXP)+j*NXP+i;
                Uc[o]=U0[o]+cdt*rU;
            }
            {   // R_V
                const float Vf=sm.Vr[c3][e0], VD=sm.Vr[c3][eD], VU=sm.Vr[c3][eU2];
                const float vf=sm.v[c3][e0], vD=sm.v[c3][eD], vU=sm.v[c3][eU2];
                const float K0=0.5f*(sm.Ur[c3][eD]+sm.Ur[c3][e0])*0.5f*(sm.v[c3][eL]+vf);
                const float K1=0.5f*(sm.Ur[c3][eD+1]+sm.Ur[c3][eR])*0.5f*(vf+sm.v[c3][eR]);
                float rV=-(K1-K0)/DXC;
                rV+=-(0.5f*(Vf+VU)*0.5f*(vf+vU)-0.5f*(VD+Vf)*0.5f*(vD+vf))/DYC;
                float H0=0.f,H1=0.f;
                if(kc>=1) H0=0.5f*(sm.Om[cm][eD]+sm.Om[cm][e0])*0.5f*(sm.v[cm][e0]+vf);
                if(kc<NZ-1) H1=0.5f*(sm.Om[c3][eD]+sm.Om[c3][e0])*0.5f*(vf+sm.v[cp][e0]);
                rV+=-(H1-H0)/DZF;
                const float mufy=0.5f*(sm.mu[c3][eD]+sm.mu[c3][e0]);
                const float alfy=0.5f*(sm.al[c3][eD]+sm.al[c3][e0]);
                const float dpy=(sm.p[c3][e0]-sm.p[c3][eD])/DYC;
                const float pjmA=(kc==0)?c.Pt[gjm*NX+i]:sm.p[cm][eD];
                const float pjjA=(kc==0)?c.Pt[j*NX+i]  :sm.p[cm][e0];
                const float pjmB=(kc==NZ-1)?c.Ps[gjm*NX+i]:sm.p[cp][eD];
                const float pjjB=(kc==NZ-1)?c.Ps[j*NX+i]  :sm.p[cp][e0];
                const float Py0=0.5f*(0.5f*(pjmA+sm.p[c3][eD])+0.5f*(pjjA+sm.p[c3][e0]));
                const float Py1=0.5f*(0.5f*(sm.p[c3][eD]+pjmB)+0.5f*(sm.p[c3][e0]+pjjB));
                rV+=-mufy*alfy*dpy-((Py1-Py0)/DZF)*((SM_PHIH(kc,e0)-SM_PHIH(kc,eD))/DYC);
                const int o=kc*(NYP*NX)+j*NX+i;
                Vc[o]=V0[o]+cdt*rV;
            }
            {   // R_Theta / R_Mu
                const float th0=sm.th[c3][e0];
                float rT=-(sm.Ur[c3][eR]*0.5f*(th0+sm.th[c3][eR])
                          -sm.Ur[c3][e0]*0.5f*(sm.th[c3][eL]+th0))/DXC;
                rT+=-(sm.Vr[c3][eU2]*0.5f*(th0+sm.th[c3][eU2])
                     -sm.Vr[c3][e0]*0.5f*(sm.th[c3][eD]+th0))/DYC;
                float OmD=0.f,OmU=0.f,Z0=0.f,Z1=0.f;
                if(kc>=1){OmD=sm.Om[cm][e0]; Z0=OmD*0.5f*(sm.th[cm][e0]+th0);}
                if(kc<NZ-1){OmU=sm.Om[c3][e0]; Z1=OmU*0.5f*(th0+sm.th[cp][e0]);}
                rT+=-(Z1-Z0)/DZF;
                const float rM=-(sm.Ur[c3][eR]-sm.Ur[c3][e0])/DXC
                              -(sm.Vr[c3][eU2]-sm.Vr[c3][e0])/DYC
                              -(OmU-OmD)/DZF;
                const int o=kc*PC+j*NX+i;
                Tc[o]=T0[o]+cdt*rT;
                Mc[o]=M0[o]+cdt*rM;
            }
        }

        const int ki=L-2;
        if(ki>=c0 && ki<w1){
            const int wi=ki%3, wm=(ki+2)%3, wp=(ki+1)%3;
            const int cA=ki%3, cB=(ki+1)%3;
            const float w0=sm.w[wi][e0];
            float rW=-(0.5f*(sm.Ur[cA][eR]+sm.Ur[cB][eR])*0.5f*(w0+sm.w[wi][eR])
                      -0.5f*(sm.Ur[cA][e0]+sm.Ur[cB][e0])*0.5f*(sm.w[wi][eL]+w0))/DXC;
            rW+=-(0.5f*(sm.Vr[cA][eU2]+sm.Vr[cB][eU2])*0.5f*(w0+sm.w[wi][eU2])
                 -0.5f*(sm.Vr[cA][e0]+sm.Vr[cB][e0])*0.5f*(sm.w[wi][eD]+w0))/DYC;
            const float OmB=sm.Om[wi][e0];
            const float OmA=(ki>=1)?sm.Om[wm][e0]:0.f;
            const float OmC=(ki<NZW-1)?sm.Om[wp][e0]:0.f;
            const float wA=(ki>=1)?sm.w[wm][e0]:0.f;
            const float wC=(ki<NZW-1)?sm.w[wp][e0]:0.f;
            rW+=-(0.5f*(OmB+OmC)*0.5f*(w0+wC)-0.5f*(OmA+OmB)*0.5f*(wA+w0))/DZF;
            rW+=GRAV*((sm.p[cB][e0]-sm.p[cA][e0])/DZF
                      -0.5f*(sm.mu[cA][e0]+sm.mu[cB][e0]));
            const int fP=(ki+1)&3;
            const float Ph0=sm.fr[fP][e0];
            const float PhL=sm.fr[fP][eL];
            const float PhR=sm.fr[fP][eR];
            const float PhD=sm.fr[fP][eD];
            const float PhU=sm.fr[fP][eU2];
            const float uzc=0.5f*(0.5f*(sm.u[cA][e0]+sm.u[cA][eR])
                                 +0.5f*(sm.u[cB][e0]+sm.u[cB][eR]));
            const float vzc=0.5f*(0.5f*(sm.v[cA][e0]+sm.v[cA][eU2])
                                 +0.5f*(sm.v[cB][e0]+sm.v[cB][eU2]));
            const float dxPhi=(0.5f*(Ph0+PhR)-0.5f*(PhL+Ph0))/DXC;
            const float dyPhi=(0.5f*(Ph0+PhU)-0.5f*(PhD+Ph0))/DYC;
            const float bza=0.5f*(sm.al[cA][e0]+sm.al[cB][e0]);
            const float bzm=0.5f*(sm.mu[cA][e0]+sm.mu[cB][e0]);
            const float om=__fdividef(__fdividef(-w0*GRAV,bza),bzm);
            const float rP=-uzc*dxPhi-vzc*dyPhi
                          -om*(SM_PHIH(ki+1,e0)-SM_PHIH(ki,e0))/DZF+GRAV*w0;
            const int o=ki*PC+j*NX+i;
            Wc[o]=W0[o]+cdt*rW;
            PhiC[o]=P0[o]+cdt*rP;
        }
        __syncthreads();
    }
}

// ---------------- edge helpers (exact, tiny kernels) -----------------------
__device__ __forceinline__ float e_alpha(const Ctx&c,int cc,int l){
    const float mu=c.Mu[l*PC+cc];
    const float f0=(l==0)?c.Phit[cc]:c.Phi[(l-1)*PC+cc];
    const float f1=(l==NZ-1)?c.Phis[cc]:c.Phi[l*PC+cc];
    return __fdiv_rn(-__fdiv_rn(f1-f0,DZF),mu);
}
__device__ __forceinline__ float e_press(const Ctx&c,int cc,int l){
    const float al=e_alpha(c,cc,l);
    const float th=__fdiv_rn(c.Th[l*PC+cc],c.Mu[l*PC+cc]);
    return POWF(__fdiv_rn(__fdiv_rn(RDC*th,PREF),al),1.4f)*PREF;
}
__device__ __forceinline__ float e_phih(const Ctx&c,int cc,int l){
    const float f0=(l==0)?c.Phit[cc]:c.Phi[(l-1)*PC+cc];
    const float f1=(l==NZ-1)?c.Phis[cc]:c.Phi[l*PC+cc];
    return 0.5f*(f0+f1);
}
__device__ __forceinline__ float e_pzh(const Ctx&c,int cc,int m){
    const float a=(m==0)?c.Pt[cc]:e_press(c,cc,m-1);
    const float b=(m==NZ)?c.Ps[cc]:e_press(c,cc,m);
    return 0.5f*(a+b);
}
__device__ __forceinline__ float e_Omg(const Ctx&c,int cc,int m){
    const float bzm=0.5f*(c.Mu[m*PC+cc]+c.Mu[(m+1)*PC+cc]);
    const float bza=0.5f*(e_alpha(c,cc,m)+e_alpha(c,cc,m+1));
    const float wv=__fdividef(c.W[m*PC+cc],bzm);
    return __fdividef(__fdividef(-wv*GRAV,bza),bzm)*bzm;
}
__device__ __forceinline__ float e_u(const Ctx&c,int ff,int jj,int l){
    const int ci=(ff>=NX)?0:ff;
    const int im=(ci==0)?NX-1:ci-1;
    const float mf=0.5f*(c.Mu[l*PC+jj*NX+im]+c.Mu[l*PC+jj*NX+ci]);
    return __fdividef(c.U[l*(NY*NXP)+jj*NXP+ff],mf);
}
__device__ __forceinline__ float e_v(const Ctx&c,int jf,int ii,int l){
    const int cj=(jf>=NY)?0:jf;
    const int jm=(cj==0)?NY-1:cj-1;
    const float mf=0.5f*(c.Mu[l*PC+jm*NX+ii]+c.Mu[l*PC+cj*NX+ii]);
    return __fdividef(c.V[l*(NYP*NX)+jf*NX+ii],mf);
}

__global__ __launch_bounds__(256)
void k_edgeU(Ctx c, const float* __restrict__ U0, float* __restrict__ Uc,
             const void* __restrict__ dtp, double coef)
{
    int idx=blockIdx.x*blockDim.x+threadIdx.x;
    if(idx>=NZ*NY) return;
    const int k=idx/NY, j=idx%NY;
    const float cdt=(float)((double)read_dt(dtp)*coef);
    const int im=NX-1, ii=0, cim=j*NX+im, cii=j*NX+ii;
    const int bU=k*(NY*NXP)+j*NXP;
    const float Uf=c.U[bU+384], UL=c.U[bU+383], UR=c.U[bU+0];
    const float uf=e_u(c,384,j,k), uL=e_u(c,383,j,k), uR=e_u(c,0,j,k);
    float rU=-(0.5f*(Uf+UR)*0.5f*(uf+uR)-0.5f*(UL+Uf)*0.5f*(uL+uf))/DXC;
    const int jm=(j==0)?NY-1:j-1, jp=(j==NY-1)?0:j+1;
    const int bV=k*(NYP*NX);
    const float Va0=0.5f*(c.V[bV+j*NX+im]+c.V[bV+j*NX+ii]);
    const float Va1=0.5f*(c.V[bV+(j+1)*NX+im]+c.V[bV+(j+1)*NX+ii]);
    rU+=-(Va1*0.5f*(uf+e_u(c,384,jp,k))-Va0*0.5f*(e_u(c,384,jm,k)+uf))/DYC;
    float H0=0.f,H1=0.f;
    if(k>=1) H0=0.5f*(e_Omg(c,cim,k-1)+e_Omg(c,cii,k-1))*0.5f*(e_u(c,384,j,k-1)+uf);
    if(k<NZ-1) H1=0.5f*(e_Omg(c,cim,k)+e_Omg(c,cii,k))*0.5f*(uf+e_u(c,384,j,k+1));
    rU+=-(H1-H0)/DZF;
    const float mufx=0.5f*(c.Mu[k*PC+cim]+c.Mu[k*PC+cii]);
    const float alfx=0.5f*(e_alpha(c,cim,k)+e_alpha(c,cii,k));
    const float dpx=(e_press(c,cii,k)-e_press(c,cim,k))/DXC;
    const float Px0=0.5f*(e_pzh(c,cim,k)+e_pzh(c,cii,k));
    const float Px1=0.5f*(e_pzh(c,cim,k+1)+e_pzh(c,cii,k+1));
    rU+=-mufx*alfx*dpx-((Px1-Px0)/DZF)*((e_phih(c,cii,k)-e_phih(c,cim,k))/DXC);
    const int o=bU+384;
    Uc[o]=U0[o]+cdt*rU;
}

__global__ __launch_bounds__(256)
void k_edgeV(Ctx c, const float* __restrict__ V0, float* __restrict__ Vc,
             const void* __restrict__ dtp, double coef)
{
    int idx=blockIdx.x*blockDim.x+threadIdx.x;
    if(idx>=NZ*NX) return;
    const int k=idx/NX, i=idx%NX;
    const float cdt=(float)((double)read_dt(dtp)*coef);
    const int jm=NY-1, jj=0, cjm=jm*NX+i, cjj=jj*NX+i;
    const int bV=k*(NYP*NX);
    const float Vf=c.V[bV+384*NX+i], VD=c.V[bV+383*NX+i], VU=c.V[bV+0*NX+i];
    const float vf=e_v(c,384,i,k), vD=e_v(c,383,i,k), vU=e_v(c,0,i,k);
    const int imx=(i==0)?NX-1:i-1, ipx=(i==NX-1)?0:i+1;
    const int bU=k*(NY*NXP);
    const float K0=0.5f*(c.U[bU+jm*NXP+i]+c.U[bU+jj*NXP+i])*0.5f*(e_v(c,384,imx,k)+vf);
    const float K1=0.5f*(c.U[bU+jm*NXP+i+1]+c.U[bU+jj*NXP+i+1])*0.5f*(vf+e_v(c,384,ipx,k));
    float rV=-(K1-K0)/DXC;
    rV+=-(0.5f*(Vf+VU)*0.5f*(vf+vU)-0.5f*(VD+Vf)*0.5f*(vD+vf))/DYC;
    float H0=0.f,H1=0.f;
    if(k>=1) H0=0.5f*(e_Omg(c,cjm,k-1)+e_Omg(c,cjj,k-1))*0.5f*(e_v(c,384,i,k-1)+vf);
    if(k<NZ-1) H1=0.5f*(e_Omg(c,cjm,k)+e_Omg(c,cjj,k))*0.5f*(vf+e_v(c,384,i,k+1));
    rV+=-(H1-H0)/DZF;
    const float mufy=0.5f*(c.Mu[k*PC+cjm]+c.Mu[k*PC+cjj]);
    const float alfy=0.5f*(e_alpha(c,cjm,k)+e_alpha(c,cjj,k));
    const float dpy=(e_press(c,cjj,k)-e_press(c,cjm,k))/DYC;
    const float Py0=0.5f*(e_pzh(c,cjm,k)+e_pzh(c,cjj,k));
    const float Py1=0.5f*(e_pzh(c,cjm,k+1)+e_pzh(c,cjj,k+1));
    rV+=-mufy*alfy*dpy-((Py1-Py0)/DZF)*((e_phih(c,cjj,k)-e_phih(c,cjm,k))/DYC);
    const int o=bV+384*NX+i;
    Vc[o]=V0[o]+cdt*rV;
}

// ---------------------------------------------------------------------------
extern "C" void kernel_launch(void* const* d_in, const int* in_sizes, int n_in,
                              void* d_out, int out_size)
{
    (void)in_sizes;(void)n_in;(void)out_size;
    const float* inU=(const float*)d_in[0];
    const float* inV=(const float*)d_in[1];
    const float* inW=(const float*)d_in[2];
    const float* inT=(const float*)d_in[3];
    const float* inM=(const float*)d_in[4];
    const float* inP=(const float*)d_in[5];
    const float* Phit=(const float*)d_in[6];
    const float* Phis=(const float*)d_in[7];
    const float* Pt=(const float*)d_in[8];
    const float* Ps=(const float*)d_in[9];
    const void* dtp=d_in[10];

    float *sU,*sV,*sW,*sT,*sM,*sP;
    cudaGetSymbolAddress((void**)&sU,g_sU);
    cudaGetSymbolAddress((void**)&sV,g_sV);
    cudaGetSymbolAddress((void**)&sW,g_sW);
    cudaGetSymbolAddress((void**)&sT,g_sT);
    cudaGetSymbolAddress((void**)&sM,g_sM);
    cudaGetSymbolAddress((void**)&sP,g_sP);

    float* out=(float*)d_out;
    float* oU=out; float* oV=oU+SZU; float* oW=oV+SZV;
    float* oT=oW+SZW; float* oM=oT+SZC; float* oP=oM+SZC;

    const double coefs[3]={1.0/3.0, 1.0/2.0, 1.0};
    const float *cU=inU,*cV=inV,*cW=inW,*cT=inT,*cM=inM,*cP=inP;

    dim3 grid(NX/TX, NY/TY, NCHUNK);
    const int gEU=(NZ*NY+255)/256, gEV=(NZ*NX+255)/256;

    for(int s=0;s<3;++s){
        float *dU,*dV,*dW,*dT,*dM,*dP;
        if(s<2){
            dU=sU+s*SZU; dV=sV+s*SZV; dW=sW+s*SZW;
            dT=sT+s*SZC; dM=sM+s*SZC; dP=sP+s*SZW;
        } else {
            dU=oU; dV=oV; dW=oW; dT=oT; dM=oM; dP=oP;
        }
        Ctx c{cU,cV,cW,cT,cM,cP,Phit,Phis,Pt,Ps};
        k_fused<<<grid,256>>>(c,inU,inV,inW,inT,inM,inP,
                              dU,dV,dW,dT,dM,dP,dtp,coefs[s]);
        k_edgeU<<<gEU,256>>>(c,inU,dU,dtp,coefs[s]);
        k_edgeV<<<gEV,256>>>(c,inV,dV,dtp,coefs[s]);
        cU=dU; cV=dV; cW=dW; cT=dT; cM=dM; cP=dP;
    }
}